// round 2
// baseline (speedup 1.0000x reference)
#include <cuda_runtime.h>
#include <cstddef>

#define NT 10240
#define KG 20
#define MG 512

// ---- scratch (device globals; allocation is forbidden) ----
__device__ float g_hlast[NT * 64];
__device__ float g_ssrc[NT];
__device__ float g_sdst[NT];
__device__ float g_hatt[NT * 64];
__device__ float g_hfc[NT * 64];   // layout [m][K][64]
__device__ float g_z[NT * 64];     // layout [m][K][64]
__device__ float g_r[NT * 64];     // layout [m][K][64]
__device__ float g_vec[130];       // v_dst[64] | v_src[64] | c_dst | c_src

__device__ __forceinline__ float sigf(float v) {
    return __fdividef(1.f, 1.f + __expf(-v));
}
__device__ __forceinline__ float lrelu(float v) {
    return v > 0.f ? v : 0.01f * v;
}

// Fused double GEMM: A = inA @ WAt (+bA), B = inB @ WBt (+bB), both [S x 192].
// Gate slots r,z (o<128): store A+B. n slot (o>=128): B->sgB, A->sgA.
// Warp = one sample group (broadcast input loads); output o = j*32+lane
// (stride-1 conflict-free weight loads). Inputs have stride 64.
template <int SPG>
__device__ __forceinline__ void dgemm2(
    const float* __restrict__ inA, const float* __restrict__ WAt, const float* __restrict__ bA,
    const float* __restrict__ inB, const float* __restrict__ WBt, const float* __restrict__ bB,
    float* __restrict__ sgB, float* __restrict__ sgA, int og, int sg)
{
    float accA[SPG][6], accB[SPG][6];
#pragma unroll
    for (int p = 0; p < SPG; p++)
#pragma unroll
        for (int j = 0; j < 6; j++) { accA[p][j] = 0.f; accB[p][j] = 0.f; }

#pragma unroll 4
    for (int k = 0; k < 64; k++) {
        float wA[6], wB[6];
#pragma unroll
        for (int j = 0; j < 6; j++) {
            wA[j] = WAt[k * 192 + j * 32 + og];
            wB[j] = WBt[k * 192 + j * 32 + og];
        }
#pragma unroll
        for (int p = 0; p < SPG; p++) {
            float av = inA[(sg * SPG + p) * 64 + k];
            float bv = inB[(sg * SPG + p) * 64 + k];
#pragma unroll
            for (int j = 0; j < 6; j++) {
                accA[p][j] = fmaf(av, wA[j], accA[p][j]);
                accB[p][j] = fmaf(bv, wB[j], accB[p][j]);
            }
        }
    }
#pragma unroll
    for (int p = 0; p < SPG; p++) {
        int s = sg * SPG + p;
#pragma unroll
        for (int j = 0; j < 6; j++) {
            int o = j * 32 + og;
            float A = accA[p][j] + bA[o];
            float B = accB[p][j] + bB[o];
            if (j < 4) {
                sgB[s * 192 + o] = A + B;
            } else {
                sgB[s * 192 + o] = B;
                sgA[s * 64 + (o - 128)] = A;
            }
        }
    }
}

// Fused 2-layer GRU over T steps for S samples/block, ntiles tiles/block.
// ID=6 specializes layer0 (x GEMM folded into elementwise, only h GEMM runs).
template <int ID, int S, int SPG, bool WRITE_ALL>
__global__ void __launch_bounds__(256, 1)
gru2_kernel(const float* __restrict__ x,
            const float* __restrict__ Wih0, const float* __restrict__ Whh0,
            const float* __restrict__ bih0, const float* __restrict__ bhh0,
            const float* __restrict__ Wih1, const float* __restrict__ Whh1,
            const float* __restrict__ bih1, const float* __restrict__ bhh1,
            float* __restrict__ out, int T, int ntiles)
{
    extern __shared__ float sm[];
    float* sWih0t = sm;                        // [ID][192]
    float* sWhh0t = sWih0t + ID * 192;         // [64][192]
    float* sWih1t = sWhh0t + 64 * 192;         // [64][192]
    float* sWhh1t = sWih1t + 64 * 192;         // [64][192]
    float* sb     = sWhh1t + 64 * 192;         // bih0|bhh0|bih1|bhh1
    float* sh0    = sb + 768;                  // [S][64]
    float* sh1    = sh0 + S * 64;              // [S][64]
    float* sgB    = sh1 + S * 64;              // [S][192]
    float* sgA    = sgB + S * 192;             // [S][64]
    float* sxt    = sgA + S * 64;              // [S][ID]

    const int tid = threadIdx.x;
    for (int idx = tid; idx < 64 * 192; idx += 256) {
        int k = idx / 192, o = idx % 192;
        sWhh0t[idx] = Whh0[o * 64 + k];
        sWih1t[idx] = Wih1[o * 64 + k];
        sWhh1t[idx] = Whh1[o * 64 + k];
    }
    for (int idx = tid; idx < ID * 192; idx += 256) {
        int i = idx / 192, o = idx % 192;
        sWih0t[idx] = Wih0[o * ID + i];
    }
    for (int idx = tid; idx < 192; idx += 256) {
        sb[idx] = bih0[idx]; sb[192 + idx] = bhh0[idx];
        sb[384 + idx] = bih1[idx]; sb[576 + idx] = bhh1[idx];
    }

    const int og = tid & 31, sg = tid >> 5;

    for (int tile = 0; tile < ntiles; tile++) {
        const int base = (blockIdx.x + tile * gridDim.x) * S;
        __syncthreads();
        for (int idx = tid; idx < S * 64; idx += 256) { sh0[idx] = 0.f; sh1[idx] = 0.f; }
        __syncthreads();

        for (int t = 0; t < T; t++) {
            for (int idx = tid; idx < S * ID; idx += 256) {
                int s = idx / ID, i = idx % ID;
                sxt[idx] = x[((size_t)(base + s) * T + t) * ID + i];
            }
            __syncthreads();

            // ---------------- layer 0 ----------------
            if constexpr (ID == 6) {
                float acc[SPG][6];
#pragma unroll
                for (int p = 0; p < SPG; p++)
#pragma unroll
                    for (int j = 0; j < 6; j++) acc[p][j] = 0.f;
#pragma unroll 4
                for (int k = 0; k < 64; k++) {
                    float w[6];
#pragma unroll
                    for (int j = 0; j < 6; j++) w[j] = sWhh0t[k * 192 + j * 32 + og];
#pragma unroll
                    for (int p = 0; p < SPG; p++) {
                        float hv = sh0[(sg * SPG + p) * 64 + k];
#pragma unroll
                        for (int j = 0; j < 6; j++) acc[p][j] = fmaf(hv, w[j], acc[p][j]);
                    }
                }
#pragma unroll
                for (int p = 0; p < SPG; p++) {
                    int s = sg * SPG + p;
#pragma unroll
                    for (int j = 0; j < 6; j++) {
                        int o = j * 32 + og;
                        sgB[s * 192 + o] = acc[p][j] + sb[192 + o];
                    }
                }
                __syncthreads();
                for (int idx = tid; idx < S * 64; idx += 256) {
                    int s = idx >> 6, j = idx & 63;
                    float xr = sb[j], xz = sb[64 + j], xn = sb[128 + j];
#pragma unroll
                    for (int i = 0; i < 6; i++) {
                        float xv = sxt[s * 6 + i];
                        xr = fmaf(xv, sWih0t[i * 192 + j], xr);
                        xz = fmaf(xv, sWih0t[i * 192 + 64 + j], xz);
                        xn = fmaf(xv, sWih0t[i * 192 + 128 + j], xn);
                    }
                    float r = sigf(xr + sgB[s * 192 + j]);
                    float z = sigf(xz + sgB[s * 192 + 64 + j]);
                    float nn = tanhf(xn + r * sgB[s * 192 + 128 + j]);
                    sh0[idx] = (1.f - z) * nn + z * sh0[idx];
                }
            } else {
                dgemm2<SPG>(sxt, sWih0t, sb, sh0, sWhh0t, sb + 192, sgB, sgA, og, sg);
                __syncthreads();
                for (int idx = tid; idx < S * 64; idx += 256) {
                    int s = idx >> 6, j = idx & 63;
                    float r = sigf(sgB[s * 192 + j]);
                    float z = sigf(sgB[s * 192 + 64 + j]);
                    float nn = tanhf(sgA[s * 64 + j] + r * sgB[s * 192 + 128 + j]);
                    sh0[idx] = (1.f - z) * nn + z * sh0[idx];
                }
            }
            __syncthreads();

            // ---------------- layer 1 ----------------
            dgemm2<SPG>(sh0, sWih1t, sb + 384, sh1, sWhh1t, sb + 576, sgB, sgA, og, sg);
            __syncthreads();
            for (int idx = tid; idx < S * 64; idx += 256) {
                int s = idx >> 6, j = idx & 63;
                float r = sigf(sgB[s * 192 + j]);
                float z = sigf(sgB[s * 192 + 64 + j]);
                float nn = tanhf(sgA[s * 64 + j] + r * sgB[s * 192 + 128 + j]);
                float h = (1.f - z) * nn + z * sh1[idx];
                sh1[idx] = h;
                if (WRITE_ALL)
                    out[((size_t)(base + s) * T + t) * 64 + j] = h;
                else if (t == T - 1)
                    out[(size_t)(base + s) * 64 + j] = h;
            }
        }
    }
}

// v_dst = trans_W^T a[:64], v_src = trans_W^T a[64:], plus bias dots.
__global__ void prep_kernel(const float* __restrict__ tW, const float* __restrict__ tb,
                            const float* __restrict__ a)
{
    int d = threadIdx.x;  // 64 threads
    float vd = 0.f, vs = 0.f;
    for (int o = 0; o < 64; o++) {
        vd = fmaf(tW[o * 64 + d], a[o], vd);
        vs = fmaf(tW[o * 64 + d], a[64 + o], vs);
    }
    g_vec[d] = vd; g_vec[64 + d] = vs;
    if (d == 0) {
        float cd = 0.f, cs = 0.f;
        for (int o = 0; o < 64; o++) { cd = fmaf(tb[o], a[o], cd); cs = fmaf(tb[o], a[64 + o], cs); }
        g_vec[128] = cd; g_vec[129] = cs;
    }
}

// Per-node src/dst scores: warp per node. grid = NT/8, 256 threads.
__global__ void score_kernel()
{
    int w = threadIdx.x >> 5, l = threadIdx.x & 31;
    int n = blockIdx.x * 8 + w;
    const float* hr = g_hlast + (size_t)n * 64;
    float h0 = hr[l], h1 = hr[l + 32];
    float ps = h0 * g_vec[64 + l] + h1 * g_vec[96 + l];
    float pd = h0 * g_vec[l] + h1 * g_vec[32 + l];
#pragma unroll
    for (int off = 16; off; off >>= 1) {
        ps += __shfl_xor_sync(~0u, ps, off);
        pd += __shfl_xor_sync(~0u, pd, off);
    }
    if (l == 0) { g_ssrc[n] = ps + g_vec[129]; g_sdst[n] = pd + g_vec[128]; }
}

// Dense GAT attention + aggregate + residual. grid = KG*8 (group x row-chunk).
__global__ void att_kernel()
{
    extern __shared__ float sm[];
    float* sh = sm;            // [512][64] group tile
    float* sd = sm + 512 * 64; // [512] s_dst
    int k = blockIdx.x >> 3, chunk = blockIdx.x & 7;
    int tid = threadIdx.x, l = tid & 31, w = tid >> 5;
    const float* hg = g_hlast + (size_t)k * 512 * 64;
    for (int i = tid; i < 512 * 64; i += 256) sh[i] = hg[i];
    for (int i = tid; i < 512; i += 256) sd[i] = g_sdst[k * 512 + i];
    __syncthreads();

    // group max of s_dst (lrelu monotone -> row max = lrelu(s_src_i + dmax))
    float dm = -1e30f;
    for (int i = l; i < 512; i += 32) dm = fmaxf(dm, sd[i]);
#pragma unroll
    for (int off = 16; off; off >>= 1) dm = fmaxf(dm, __shfl_xor_sync(~0u, dm, off));

    for (int rr = 0; rr < 8; rr++) {
        int i = chunk * 64 + w * 8 + rr;
        float si = g_ssrc[k * 512 + i];
        float mi = lrelu(si + dm);
        float denom = 0.f, a0 = 0.f, a1 = 0.f;
        for (int j0 = 0; j0 < 512; j0 += 32) {
            float e = __expf(lrelu(si + sd[j0 + l]) - mi);
            denom += e;
#pragma unroll
            for (int jj = 0; jj < 32; jj++) {
                float ev = __shfl_sync(~0u, e, jj);
                const float* hj = sh + (j0 + jj) * 64;
                a0 = fmaf(ev, hj[l], a0);
                a1 = fmaf(ev, hj[l + 32], a1);
            }
        }
#pragma unroll
        for (int off = 16; off; off >>= 1) denom += __shfl_xor_sync(~0u, denom, off);
        float inv = __fdividef(1.f, denom);
        float* o = g_hatt + ((size_t)k * 512 + i) * 64;
        o[l] = fmaf(a0, inv, sh[i * 64 + l]);
        o[l + 32] = fmaf(a1, inv, sh[i * 64 + l + 32]);
    }
}

// hfc = hatt @ fc_W^T + fc_b (store in [m][K][64] layout); z = tanh(hfc @ al_in_W^T + al_in_b).
__global__ void fc_kernel(const float* __restrict__ fcW, const float* __restrict__ fcb,
                          const float* __restrict__ inW, const float* __restrict__ inb)
{
    __shared__ float sWf[64 * 64], sWi[64 * 64], sbf[64], sbi[64];
    __shared__ float srow[8][64], shf[8][64];
    int tid = threadIdx.x;
    for (int i = tid; i < 4096; i += 256) {
        int o = i >> 6, d = i & 63;
        sWf[d * 64 + o] = fcW[i];
        sWi[d * 64 + o] = inW[i];
    }
    if (tid < 64) { sbf[tid] = fcb[tid]; sbi[tid] = inb[tid]; }
    __syncthreads();
    int w = tid >> 5, l = tid & 31;
    for (int it = 0; it < 16; it++) {
        int n = blockIdx.x * 128 + it * 8 + w;  // 80*128 = 10240
        const float* hr = g_hatt + (size_t)n * 64;
        srow[w][l] = hr[l]; srow[w][l + 32] = hr[l + 32];
        __syncwarp();
        float a0 = sbf[l], a1 = sbf[l + 32];
        for (int d = 0; d < 64; d++) {
            float v = srow[w][d];
            a0 = fmaf(v, sWf[d * 64 + l], a0);
            a1 = fmaf(v, sWf[d * 64 + l + 32], a1);
        }
        int kk = n >> 9, ii = n & 511;
        float* of = g_hfc + ((size_t)ii * KG + kk) * 64;
        of[l] = a0; of[l + 32] = a1;
        shf[w][l] = a0; shf[w][l + 32] = a1;
        __syncwarp();
        float z0 = sbi[l], z1 = sbi[l + 32];
        for (int d = 0; d < 64; d++) {
            float v = shf[w][d];
            z0 = fmaf(v, sWi[d * 64 + l], z0);
            z1 = fmaf(v, sWi[d * 64 + l + 32], z1);
        }
        float* oz = g_z + ((size_t)ii * KG + kk) * 64;
        oz[l] = tanhf(z0); oz[l + 32] = tanhf(z1);
        __syncwarp();
    }
}

// ALSTM attention head + final outputs. Warp per sample. grid = 64.
__global__ void head_kernel(const float* __restrict__ W1, const float* __restrict__ b1,
                            const float* __restrict__ W2,
                            const float* __restrict__ Wo, const float* __restrict__ bo,
                            const float* __restrict__ fcoW, const float* __restrict__ fcob,
                            float* __restrict__ out)
{
    __shared__ float sW1[64 * 32], sb1[32], sW2[32], sWo[128], sfw[64];
    __shared__ float rbuf[8][64], sbuf[8][20];
    int tid = threadIdx.x;
    for (int i = tid; i < 2048; i += 256) { int o = i >> 6, d = i & 63; sW1[d * 32 + o] = W1[i]; }
    if (tid < 32) { sb1[tid] = b1[tid]; sW2[tid] = W2[tid]; }
    if (tid < 128) sWo[tid] = Wo[tid];
    if (tid < 64) sfw[tid] = fcoW[tid];
    __syncthreads();
    int w = tid >> 5, l = tid & 31;
    int n = blockIdx.x * 8 + w;
    const float* rn = g_r + (size_t)n * KG * 64;

    for (int k = 0; k < KG; k++) {
        rbuf[w][l] = rn[k * 64 + l]; rbuf[w][l + 32] = rn[k * 64 + l + 32];
        __syncwarp();
        float acc = sb1[l];
        for (int d = 0; d < 64; d++) acc = fmaf(rbuf[w][d], sW1[d * 32 + l], acc);
        float p = tanhf(acc) * sW2[l];
#pragma unroll
        for (int off = 16; off; off >>= 1) p += __shfl_xor_sync(~0u, p, off);
        if (l == 0) sbuf[w][k] = p;
        __syncwarp();
    }
    // softmax over K=20
    float sv = (l < KG) ? sbuf[w][l] : -1e30f;
    float mx = sv;
#pragma unroll
    for (int off = 16; off; off >>= 1) mx = fmaxf(mx, __shfl_xor_sync(~0u, mx, off));
    float e = (l < KG) ? __expf(sv - mx) : 0.f;
    float ssum = e;
#pragma unroll
    for (int off = 16; off; off >>= 1) ssum += __shfl_xor_sync(~0u, ssum, off);
    if (l < KG) sbuf[w][l] = __fdividef(e, ssum);
    __syncwarp();

    float a0 = 0.f, a1 = 0.f;
    for (int k = 0; k < KG; k++) {
        float wk = sbuf[w][k];
        a0 = fmaf(wk, rn[k * 64 + l], a0);
        a1 = fmaf(wk, rn[k * 64 + l + 32], a1);
    }
    float rl0 = rn[19 * 64 + l], rl1 = rn[19 * 64 + l + 32];
    float part = rl0 * sWo[l] + rl1 * sWo[l + 32] + a0 * sWo[64 + l] + a1 * sWo[96 + l];
#pragma unroll
    for (int off = 16; off; off >>= 1) part += __shfl_xor_sync(~0u, part, off);
    if (l == 0) out[n] = part + bo[0];

    // pred (uses fc output at k = K-1)
    const float* hf = g_hfc + (size_t)n * KG * 64 + 19 * 64;
    float pp = lrelu(hf[l]) * sfw[l] + lrelu(hf[l + 32]) * sfw[l + 32];
#pragma unroll
    for (int off = 16; off; off >>= 1) pp += __shfl_xor_sync(~0u, pp, off);
    if (l == 0) out[512 + n] = pp + fcob[0];
}

extern "C" void kernel_launch(void* const* d_in, const int* in_sizes, int n_in,
                              void* d_out, int out_size)
{
    const float* x      = (const float*)d_in[0];
    const float* Wih0   = (const float*)d_in[1];
    const float* Whh0   = (const float*)d_in[2];
    const float* bih0   = (const float*)d_in[3];
    const float* bhh0   = (const float*)d_in[4];
    const float* Wih1   = (const float*)d_in[5];
    const float* Whh1   = (const float*)d_in[6];
    const float* bih1   = (const float*)d_in[7];
    const float* bhh1   = (const float*)d_in[8];
    const float* transW = (const float*)d_in[9];
    const float* transb = (const float*)d_in[10];
    const float* avec   = (const float*)d_in[11];
    const float* fcW    = (const float*)d_in[12];
    const float* fcb    = (const float*)d_in[13];
    const float* fcoW   = (const float*)d_in[14];
    const float* fcob   = (const float*)d_in[15];
    const float* inW    = (const float*)d_in[16];
    const float* inb    = (const float*)d_in[17];
    const float* aWih0  = (const float*)d_in[18];
    const float* aWhh0  = (const float*)d_in[19];
    const float* abih0  = (const float*)d_in[20];
    const float* abhh0  = (const float*)d_in[21];
    const float* aWih1  = (const float*)d_in[22];
    const float* aWhh1  = (const float*)d_in[23];
    const float* abih1  = (const float*)d_in[24];
    const float* abhh1  = (const float*)d_in[25];
    const float* att1W  = (const float*)d_in[26];
    const float* att1b  = (const float*)d_in[27];
    const float* att2W  = (const float*)d_in[28];
    const float* outW   = (const float*)d_in[29];
    const float* outb   = (const float*)d_in[30];
    float* out = (float*)d_out;

    void *p_hlast, *p_z, *p_r;
    cudaGetSymbolAddress(&p_hlast, g_hlast);
    cudaGetSymbolAddress(&p_z, g_z);
    cudaGetSymbolAddress(&p_r, g_r);

    const size_t smemE   = (size_t)(6 * 192 + 3 * 64 * 192 + 768 + 40 * (64 + 64 + 192 + 64 + 6)) * 4;
    const size_t smemA   = (size_t)(4 * 64 * 192 + 768 + 8 * (64 + 64 + 192 + 64 + 64)) * 4;
    const size_t smemAtt = (size_t)(512 * 64 + 512) * 4;

    cudaFuncSetAttribute(gru2_kernel<6, 40, 5, false>,
                         cudaFuncAttributeMaxDynamicSharedMemorySize, (int)smemE);
    cudaFuncSetAttribute(gru2_kernel<64, 8, 1, true>,
                         cudaFuncAttributeMaxDynamicSharedMemorySize, (int)smemA);
    cudaFuncSetAttribute(att_kernel,
                         cudaFuncAttributeMaxDynamicSharedMemorySize, (int)smemAtt);

    // ---- encoder: fused 2-layer GRU, 128 blocks x 2 tiles of 40 samples ----
    gru2_kernel<6, 40, 5, false><<<128, 256, smemE>>>(
        x, Wih0, Whh0, bih0, bhh0, Wih1, Whh1, bih1, bhh1,
        (float*)p_hlast, 60, 2);

    // ---- GAT attention ----
    prep_kernel<<<1, 64>>>(transW, transb, avec);
    score_kernel<<<1280, 256>>>();
    att_kernel<<<160, 256, smemAtt>>>();

    // ---- fc + al_in tanh ----
    fc_kernel<<<80, 256>>>(fcW, fcb, inW, inb);

    // ---- ALSTM: fused 2-layer GRU over K=20, batch 512 ----
    gru2_kernel<64, 8, 1, true><<<64, 256, smemA>>>(
        (const float*)p_z, aWih0, aWhh0, abih0, abhh0, aWih1, aWhh1, abih1, abhh1,
        (float*)p_r, 20, 1);

    // ---- head: ALSTM attention + outputs ----
    head_kernel<<<64, 256>>>(att1W, att1b, att2W, outW, outb, fcoW, fcob, out);
}

// round 4
// speedup vs baseline: 1.0537x; 1.0537x over previous
#include <cuda_runtime.h>
#include <cstddef>

#define NT 10240
#define KG 20
#define MG 512

typedef unsigned long long u64;

// ---- scratch (device globals; allocation is forbidden) ----
__device__ float g_hlast[NT * 64];
__device__ float g_ssrc[NT];
__device__ float g_sdst[NT];
__device__ float g_hatt[NT * 64];
__device__ float g_hfc[NT * 64];   // layout [m][K][64]
__device__ float g_z[NT * 64];     // layout [m][K][64]
__device__ float g_r[NT * 64];     // layout [m][K][64]
__device__ float g_vec[130];       // v_dst[64] | v_src[64] | c_dst | c_src

__device__ __forceinline__ float sige(float v) {
    return __fdividef(1.f, 1.f + __expf(-v));
}
// tanh(x) = 1 - 2/(e^{2x}+1); NaN-safe at +/-inf, rel err ~1e-6
__device__ __forceinline__ float tanhe(float v) {
    return 1.f - __fdividef(2.f, __expf(2.f * v) + 1.f);
}
__device__ __forceinline__ float lrelu(float v) { return v > 0.f ? v : 0.01f * v; }

__device__ __forceinline__ void fma2(u64& d, u64 a, u64 b) {
    asm("fma.rn.f32x2 %0, %1, %2, %3;" : "=l"(d) : "l"(a), "l"(b), "l"(d));
}
__device__ __forceinline__ float unpack_sum(u64 a, float bias) {
    float lo = __uint_as_float((unsigned)(a & 0xffffffffu));
    float hi = __uint_as_float((unsigned)(a >> 32));
    return lo + hi + bias;
}

// One GEMM pass out[S x 192] += in[S x 64] @ W (k-paired layout) using f32x2.
// MODE 0: write all 192 -> sgB (input pass).
// MODE 1: add into sgB for o<128, write n-part -> sgA (hidden pass after MODE0).
// MODE 2: write sgB for o<128, n-part -> sgA (hidden-only, x folded in EW).
// Warp = sample group sg (broadcast input loads); lane og owns o = j*32+og.
template <int SPG, int MODE>
__device__ __forceinline__ void gpass(const float* __restrict__ inp,
                                      const float* __restrict__ Wp,
                                      const float* __restrict__ bias,
                                      float* __restrict__ sgB,
                                      float* __restrict__ sgA,
                                      int og, int sg)
{
    u64 acc[SPG][6];
#pragma unroll
    for (int p = 0; p < SPG; p++)
#pragma unroll
        for (int j = 0; j < 6; j++) acc[p][j] = 0ull;

    const u64* W2 = reinterpret_cast<const u64*>(Wp);
    const u64* I2 = reinterpret_cast<const u64*>(inp);
#pragma unroll 4
    for (int k2 = 0; k2 < 32; k2++) {
        u64 w[6];
#pragma unroll
        for (int j = 0; j < 6; j++) w[j] = W2[(k2 * 6 + j) * 32 + og];
#pragma unroll
        for (int p = 0; p < SPG; p++) {
            u64 a = I2[(sg * SPG + p) * 32 + k2];
#pragma unroll
            for (int j = 0; j < 6; j++) fma2(acc[p][j], a, w[j]);
        }
    }
#pragma unroll
    for (int p = 0; p < SPG; p++) {
        int s = sg * SPG + p;
#pragma unroll
        for (int j = 0; j < 6; j++) {
            int o = j * 32 + og;
            float r = unpack_sum(acc[p][j], bias[o]);
            if (MODE == 0) {
                sgB[s * 192 + o] = r;
            } else if (j < 4) {
                if (MODE == 1) sgB[s * 192 + o] += r;
                else           sgB[s * 192 + o] = r;
            } else {
                sgA[s * 64 + (o - 128)] = r;
            }
        }
    }
}

// Fused 2-layer GRU over T steps, S samples/block, ntiles tiles/block.
// ID=6 (encoder): layer0 hidden GEMM only, x-part folded into elementwise.
template <int ID, int S, int SPG, bool WRITE_ALL>
__global__ void __launch_bounds__(256, 1)
gru2_kernel(const float* __restrict__ x,
            const float* __restrict__ Wih0, const float* __restrict__ Whh0,
            const float* __restrict__ bih0, const float* __restrict__ bhh0,
            const float* __restrict__ Wih1, const float* __restrict__ Whh1,
            const float* __restrict__ bih1, const float* __restrict__ bhh1,
            float* __restrict__ out, int T, int ntiles)
{
    extern __shared__ float sm[];
    constexpr int W0SZ = (ID == 6) ? 6 * 192 : 64 * 192;
    float* sWih0 = sm;                     // ID==6: [i][192]; else paired
    float* sWhh0 = sWih0 + W0SZ;           // paired [k2][j][og2]
    float* sWih1 = sWhh0 + 64 * 192;
    float* sWhh1 = sWih1 + 64 * 192;
    float* sb    = sWhh1 + 64 * 192;       // bih0|bhh0|bih1|bhh1
    float* sh0   = sb + 768;               // [S][64]
    float* sh1   = sh0 + S * 64;           // [S][64]
    float* sgB   = sh1 + S * 64;           // [S][192]
    float* sgA   = sgB + S * 192;          // [S][64]
    float* sxt   = sgA + S * 64;           // [S][ID]

    const int tid = threadIdx.x;

    // k-paired weight load: sW[(k2*6+j)*64 + og*2 + c] = W[(j*32+og)*64 + 2*k2+c]
    for (int idx = tid; idx < 64 * 192; idx += 256) {
        int og2 = idx & 63;
        int j = (idx >> 6) % 6;
        int k2 = idx / 384;
        int o = j * 32 + (og2 >> 1);
        int k = k2 * 2 + (og2 & 1);
        sWhh0[idx] = Whh0[o * 64 + k];
        sWih1[idx] = Wih1[o * 64 + k];
        sWhh1[idx] = Whh1[o * 64 + k];
        if (ID == 64) sWih0[idx] = Wih0[o * 64 + k];
    }
    if (ID == 6) {
        for (int idx = tid; idx < 6 * 192; idx += 256) {
            int i = idx / 192, o = idx % 192;
            sWih0[idx] = Wih0[o * 6 + i];
        }
    }
    for (int idx = tid; idx < 192; idx += 256) {
        sb[idx] = bih0[idx]; sb[192 + idx] = bhh0[idx];
        sb[384 + idx] = bih1[idx]; sb[576 + idx] = bhh1[idx];
    }

    const int og = tid & 31, sg = tid >> 5;
    constexpr int XR = (S * ID + 255) / 256;

    for (int tile = 0; tile < ntiles; tile++) {
        const int base = (blockIdx.x + tile * gridDim.x) * S;
        __syncthreads();
        for (int idx = tid; idx < S * 64; idx += 256) { sh0[idx] = 0.f; sh1[idx] = 0.f; }
        for (int idx = tid; idx < S * ID; idx += 256) {
            int s = idx / ID, i = idx % ID;
            sxt[idx] = x[((size_t)(base + s) * T) * ID + i];
        }
        __syncthreads();

        for (int t = 0; t < T; t++) {
            // prefetch x(t+1) into registers (latency hidden under GEMMs)
            float xreg[XR];
            if (t + 1 < T) {
#pragma unroll
                for (int r = 0; r < XR; r++) {
                    int idx = tid + r * 256;
                    if (idx < S * ID) {
                        int s = idx / ID, i = idx % ID;
                        xreg[r] = x[((size_t)(base + s) * T + t + 1) * ID + i];
                    }
                }
            }

            // ---------------- layer 0 ----------------
            if constexpr (ID == 6) {
                gpass<SPG, 2>(sh0, sWhh0, sb + 192, sgB, sgA, og, sg);
                __syncthreads();
                for (int idx = tid; idx < S * 64; idx += 256) {
                    int s = idx >> 6, j = idx & 63;
                    float xr = sb[j], xz = sb[64 + j], xn = sb[128 + j];
#pragma unroll
                    for (int i = 0; i < 6; i++) {
                        float xv = sxt[s * 6 + i];
                        xr = fmaf(xv, sWih0[i * 192 + j], xr);
                        xz = fmaf(xv, sWih0[i * 192 + 64 + j], xz);
                        xn = fmaf(xv, sWih0[i * 192 + 128 + j], xn);
                    }
                    float r = sige(xr + sgB[s * 192 + j]);
                    float z = sige(xz + sgB[s * 192 + 64 + j]);
                    float nn = tanhe(xn + r * sgA[s * 64 + j]);
                    sh0[idx] = nn + z * (sh0[idx] - nn);
                }
            } else {
                gpass<SPG, 0>(sxt, sWih0, sb,       sgB, sgA, og, sg);
                gpass<SPG, 1>(sh0, sWhh0, sb + 192, sgB, sgA, og, sg);
                __syncthreads();
                for (int idx = tid; idx < S * 64; idx += 256) {
                    int s = idx >> 6, j = idx & 63;
                    float r = sige(sgB[s * 192 + j]);
                    float z = sige(sgB[s * 192 + 64 + j]);
                    float nn = tanhe(sgB[s * 192 + 128 + j] + r * sgA[s * 64 + j]);
                    sh0[idx] = nn + z * (sh0[idx] - nn);
                }
            }
            __syncthreads();

            // store prefetched x (sxt not read again until next layer0 EW,
            // separated by two more barriers)
            if (t + 1 < T) {
#pragma unroll
                for (int r = 0; r < XR; r++) {
                    int idx = tid + r * 256;
                    if (idx < S * ID) sxt[idx] = xreg[r];
                }
            }

            // ---------------- layer 1 ----------------
            gpass<SPG, 0>(sh0, sWih1, sb + 384, sgB, sgA, og, sg);
            gpass<SPG, 1>(sh1, sWhh1, sb + 576, sgB, sgA, og, sg);
            __syncthreads();
            for (int idx = tid; idx < S * 64; idx += 256) {
                int s = idx >> 6, j = idx & 63;
                float r = sige(sgB[s * 192 + j]);
                float z = sige(sgB[s * 192 + 64 + j]);
                float nn = tanhe(sgB[s * 192 + 128 + j] + r * sgA[s * 64 + j]);
                float h = nn + z * (sh1[idx] - nn);
                sh1[idx] = h;
                if (WRITE_ALL)
                    out[((size_t)(base + s) * T + t) * 64 + j] = h;
                else if (t == T - 1)
                    out[(size_t)(base + s) * 64 + j] = h;
            }
            __syncthreads();
        }
    }
}

// v_dst = trans_W^T a[:64], v_src = trans_W^T a[64:], plus bias dots.
__global__ void prep_kernel(const float* __restrict__ tW, const float* __restrict__ tb,
                            const float* __restrict__ a)
{
    int d = threadIdx.x;  // 64 threads
    float vd = 0.f, vs = 0.f;
    for (int o = 0; o < 64; o++) {
        vd = fmaf(tW[o * 64 + d], a[o], vd);
        vs = fmaf(tW[o * 64 + d], a[64 + o], vs);
    }
    g_vec[d] = vd; g_vec[64 + d] = vs;
    if (d == 0) {
        float cd = 0.f, cs = 0.f;
        for (int o = 0; o < 64; o++) { cd = fmaf(tb[o], a[o], cd); cs = fmaf(tb[o], a[64 + o], cs); }
        g_vec[128] = cd; g_vec[129] = cs;
    }
}

// Per-node src/dst scores: warp per node. grid = NT/8, 256 threads.
__global__ void score_kernel()
{
    int w = threadIdx.x >> 5, l = threadIdx.x & 31;
    int n = blockIdx.x * 8 + w;
    const float* hr = g_hlast + (size_t)n * 64;
    float h0 = hr[l], h1 = hr[l + 32];
    float ps = h0 * g_vec[64 + l] + h1 * g_vec[96 + l];
    float pd = h0 * g_vec[l] + h1 * g_vec[32 + l];
#pragma unroll
    for (int off = 16; off; off >>= 1) {
        ps += __shfl_xor_sync(~0u, ps, off);
        pd += __shfl_xor_sync(~0u, pd, off);
    }
    if (l == 0) { g_ssrc[n] = ps + g_vec[129]; g_sdst[n] = pd + g_vec[128]; }
}

// Dense GAT attention + aggregate + residual. grid = KG*8 (group x 64-row chunk).
// Warp per row: exp row -> smem, then f32x2 aggregation over d-pairs.
__global__ void att_kernel()
{
    extern __shared__ float sm[];
    float* sh = sm;               // [512][64] group tile
    float* sd = sm + 512 * 64;    // [512] s_dst
    float* se = sd + 512;         // [8][512] per-warp exp rows
    int k = blockIdx.x >> 3, chunk = blockIdx.x & 7;
    int tid = threadIdx.x, l = tid & 31, w = tid >> 5;
    const float* hg = g_hlast + (size_t)k * 512 * 64;
    for (int i = tid; i < 512 * 64; i += 256) sh[i] = hg[i];
    for (int i = tid; i < 512; i += 256) sd[i] = g_sdst[k * 512 + i];
    __syncthreads();

    // group max of s_dst (lrelu monotone -> row max = lrelu(s_src_i + dmax))
    float dm = -1e30f;
    for (int i = l; i < 512; i += 32) dm = fmaxf(dm, sd[i]);
#pragma unroll
    for (int off = 16; off; off >>= 1) dm = fmaxf(dm, __shfl_xor_sync(~0u, dm, off));

    float* ew = se + w * 512;
    const u64* sh2 = reinterpret_cast<const u64*>(sh);
    for (int rr = 0; rr < 8; rr++) {
        int i = chunk * 64 + w * 8 + rr;
        float si = g_ssrc[k * 512 + i];
        float mi = lrelu(si + dm);
        float den = 0.f;
        for (int j = l; j < 512; j += 32) {
            float e = __expf(lrelu(si + sd[j]) - mi);
            ew[j] = e;
            den += e;
        }
#pragma unroll
        for (int off = 16; off; off >>= 1) den += __shfl_xor_sync(~0u, den, off);
        __syncwarp();

        u64 acc = 0ull;
#pragma unroll 4
        for (int j = 0; j < 512; j++) {
            u64 e2 = (u64)__float_as_uint(ew[j]);
            e2 |= e2 << 32;
            fma2(acc, e2, sh2[j * 32 + l]);
        }
        float inv = __fdividef(1.f, den);
        float a0 = __uint_as_float((unsigned)(acc & 0xffffffffu));
        float a1 = __uint_as_float((unsigned)(acc >> 32));
        float* o = g_hatt + ((size_t)k * 512 + i) * 64;
        o[2 * l]     = fmaf(a0, inv, sh[i * 64 + 2 * l]);
        o[2 * l + 1] = fmaf(a1, inv, sh[i * 64 + 2 * l + 1]);
        __syncwarp();
    }
}

// hfc = hatt @ fc_W^T + fc_b ([m][K][64] layout); z = tanh(hfc @ al_in_W^T + al_in_b).
__global__ void fc_kernel(const float* __restrict__ fcW, const float* __restrict__ fcb,
                          const float* __restrict__ inW, const float* __restrict__ inb)
{
    __shared__ float sWf[64 * 64], sWi[64 * 64], sbf[64], sbi[64];
    __shared__ float srow[8][64], shf[8][64];
    int tid = threadIdx.x;
    for (int i = tid; i < 4096; i += 256) {
        int o = i >> 6, d = i & 63;
        sWf[d * 64 + o] = fcW[i];
        sWi[d * 64 + o] = inW[i];
    }
    if (tid < 64) { sbf[tid] = fcb[tid]; sbi[tid] = inb[tid]; }
    __syncthreads();
    int w = tid >> 5, l = tid & 31;
    for (int it = 0; it < 16; it++) {
        int n = blockIdx.x * 128 + it * 8 + w;  // 80*128 = 10240
        const float* hr = g_hatt + (size_t)n * 64;
        srow[w][l] = hr[l]; srow[w][l + 32] = hr[l + 32];
        __syncwarp();
        float a0 = sbf[l], a1 = sbf[l + 32];
        for (int d = 0; d < 64; d++) {
            float v = srow[w][d];
            a0 = fmaf(v, sWf[d * 64 + l], a0);
            a1 = fmaf(v, sWf[d * 64 + l + 32], a1);
        }
        int kk = n >> 9, ii = n & 511;
        float* of = g_hfc + ((size_t)ii * KG + kk) * 64;
        of[l] = a0; of[l + 32] = a1;
        shf[w][l] = a0; shf[w][l + 32] = a1;
        __syncwarp();
        float z0 = sbi[l], z1 = sbi[l + 32];
        for (int d = 0; d < 64; d++) {
            float v = shf[w][d];
            z0 = fmaf(v, sWi[d * 64 + l], z0);
            z1 = fmaf(v, sWi[d * 64 + l + 32], z1);
        }
        float* oz = g_z + ((size_t)ii * KG + kk) * 64;
        oz[l] = tanhe(z0); oz[l + 32] = tanhe(z1);
        __syncwarp();
    }
}

// ALSTM attention head + final outputs. Warp per sample. grid = 64.
__global__ void head_kernel(const float* __restrict__ W1, const float* __restrict__ b1,
                            const float* __restrict__ W2,
                            const float* __restrict__ Wo, const float* __restrict__ bo,
                            const float* __restrict__ fcoW, const float* __restrict__ fcob,
                            float* __restrict__ out)
{
    __shared__ float sW1[64 * 32], sb1[32], sW2[32], sWo[128], sfw[64];
    __shared__ float rbuf[8][64], sbuf[8][20];
    int tid = threadIdx.x;
    for (int i = tid; i < 2048; i += 256) { int o = i >> 6, d = i & 63; sW1[d * 32 + o] = W1[i]; }
    if (tid < 32) { sb1[tid] = b1[tid]; sW2[tid] = W2[tid]; }
    if (tid < 128) sWo[tid] = Wo[tid];
    if (tid < 64) sfw[tid] = fcoW[tid];
    __syncthreads();
    int w = tid >> 5, l = tid & 31;
    int n = blockIdx.x * 8 + w;
    const float* rn = g_r + (size_t)n * KG * 64;

    for (int k = 0; k < KG; k++) {
        rbuf[w][l] = rn[k * 64 + l]; rbuf[w][l + 32] = rn[k * 64 + l + 32];
        __syncwarp();
        float acc = sb1[l];
        for (int d = 0; d < 64; d++) acc = fmaf(rbuf[w][d], sW1[d * 32 + l], acc);
        float p = tanhe(acc) * sW2[l];
#pragma unroll
        for (int off = 16; off; off >>= 1) p += __shfl_xor_sync(~0u, p, off);
        if (l == 0) sbuf[w][k] = p;
        __syncwarp();
    }
    float sv = (l < KG) ? sbuf[w][l] : -1e30f;
    float mx = sv;
#pragma unroll
    for (int off = 16; off; off >>= 1) mx = fmaxf(mx, __shfl_xor_sync(~0u, mx, off));
    float e = (l < KG) ? __expf(sv - mx) : 0.f;
    float ssum = e;
#pragma unroll
    for (int off = 16; off; off >>= 1) ssum += __shfl_xor_sync(~0u, ssum, off);
    if (l < KG) sbuf[w][l] = __fdividef(e, ssum);
    __syncwarp();

    float a0 = 0.f, a1 = 0.f;
    for (int k = 0; k < KG; k++) {
        float wk = sbuf[w][k];
        a0 = fmaf(wk, rn[k * 64 + l], a0);
        a1 = fmaf(wk, rn[k * 64 + l + 32], a1);
    }
    float rl0 = rn[19 * 64 + l], rl1 = rn[19 * 64 + l + 32];
    float part = rl0 * sWo[l] + rl1 * sWo[l + 32] + a0 * sWo[64 + l] + a1 * sWo[96 + l];
#pragma unroll
    for (int off = 16; off; off >>= 1) part += __shfl_xor_sync(~0u, part, off);
    if (l == 0) out[n] = part + bo[0];

    const float* hf = g_hfc + (size_t)n * KG * 64 + 19 * 64;
    float pp = lrelu(hf[l]) * sfw[l] + lrelu(hf[l + 32]) * sfw[l + 32];
#pragma unroll
    for (int off = 16; off; off >>= 1) pp += __shfl_xor_sync(~0u, pp, off);
    if (l == 0) out[512 + n] = pp + fcob[0];
}

extern "C" void kernel_launch(void* const* d_in, const int* in_sizes, int n_in,
                              void* d_out, int out_size)
{
    const float* x      = (const float*)d_in[0];
    const float* Wih0   = (const float*)d_in[1];
    const float* Whh0   = (const float*)d_in[2];
    const float* bih0   = (const float*)d_in[3];
    const float* bhh0   = (const float*)d_in[4];
    const float* Wih1   = (const float*)d_in[5];
    const float* Whh1   = (const float*)d_in[6];
    const float* bih1   = (const float*)d_in[7];
    const float* bhh1   = (const float*)d_in[8];
    const float* transW = (const float*)d_in[9];
    const float* transb = (const float*)d_in[10];
    const float* avec   = (const float*)d_in[11];
    const float* fcW    = (const float*)d_in[12];
    const float* fcb    = (const float*)d_in[13];
    const float* fcoW   = (const float*)d_in[14];
    const float* fcob   = (const float*)d_in[15];
    const float* inW    = (const float*)d_in[16];
    const float* inb    = (const float*)d_in[17];
    const float* aWih0  = (const float*)d_in[18];
    const float* aWhh0  = (const float*)d_in[19];
    const float* abih0  = (const float*)d_in[20];
    const float* abhh0  = (const float*)d_in[21];
    const float* aWih1  = (const float*)d_in[22];
    const float* aWhh1  = (const float*)d_in[23];
    const float* abih1  = (const float*)d_in[24];
    const float* abhh1  = (const float*)d_in[25];
    const float* att1W  = (const float*)d_in[26];
    const float* att1b  = (const float*)d_in[27];
    const float* att2W  = (const float*)d_in[28];
    const float* outW   = (const float*)d_in[29];
    const float* outb   = (const float*)d_in[30];
    float* out = (float*)d_out;

    void *p_hlast, *p_z, *p_r;
    cudaGetSymbolAddress(&p_hlast, g_hlast);
    cudaGetSymbolAddress(&p_z, g_z);
    cudaGetSymbolAddress(&p_r, g_r);

    const size_t smemE   = (size_t)(6 * 192 + 3 * 64 * 192 + 768 + 40 * (64 + 64 + 192 + 64 + 6)) * 4;
    const size_t smemA   = (size_t)(4 * 64 * 192 + 768 + 8 * (64 + 64 + 192 + 64 + 64)) * 4;
    const size_t smemAtt = (size_t)(512 * 64 + 512 + 8 * 512) * 4;

    cudaFuncSetAttribute(gru2_kernel<6, 40, 5, false>,
                         cudaFuncAttributeMaxDynamicSharedMemorySize, (int)smemE);
    cudaFuncSetAttribute(gru2_kernel<64, 8, 1, true>,
                         cudaFuncAttributeMaxDynamicSharedMemorySize, (int)smemA);
    cudaFuncSetAttribute(att_kernel,
                         cudaFuncAttributeMaxDynamicSharedMemorySize, (int)smemAtt);

    // ---- encoder: fused 2-layer GRU, 128 blocks x 2 tiles of 40 samples ----
    gru2_kernel<6, 40, 5, false><<<128, 256, smemE>>>(
        x, Wih0, Whh0, bih0, bhh0, Wih1, Whh1, bih1, bhh1,
        (float*)p_hlast, 60, 2);

    // ---- GAT attention ----
    prep_kernel<<<1, 64>>>(transW, transb, avec);
    score_kernel<<<1280, 256>>>();
    att_kernel<<<160, 256, smemAtt>>>();

    // ---- fc + al_in tanh ----
    fc_kernel<<<80, 256>>>(fcW, fcb, inW, inb);

    // ---- ALSTM: fused 2-layer GRU over K=20, batch 512 ----
    gru2_kernel<64, 8, 1, true><<<64, 256, smemA>>>(
        (const float*)p_z, aWih0, aWhh0, abih0, abhh0, aWih1, aWhh1, abih1, abhh1,
        (float*)p_r, 20, 1);

    // ---- head: ALSTM attention + outputs ----
    head_kernel<<<64, 256>>>(att1W, att1b, att2W, outW, outb, fcoW, fcob, out);
}

// round 5
// speedup vs baseline: 1.3755x; 1.3054x over previous
#include <cuda_runtime.h>
#include <cstddef>

#define NT 10240
#define KG 20
#define MG 512

typedef unsigned long long u64;

// ---- scratch (device globals; allocation is forbidden) ----
__device__ float g_hlast[NT * 64];
__device__ float g_ssrc[NT];
__device__ float g_sdst[NT];
__device__ float g_hatt[NT * 64];
__device__ float g_hfc[NT * 64];   // layout [m][K][64]
__device__ float g_z[NT * 64];     // layout [m][K][64]
__device__ float g_r[NT * 64];     // layout [m][K][64]
__device__ float g_vec[130];       // v_dst[64] | v_src[64] | c_dst | c_src

__device__ __forceinline__ float sige(float v) {
    return __fdividef(1.f, 1.f + __expf(-v));
}
// tanh(x) = 1 - 2/(e^{2x}+1); NaN-safe at +/-inf, rel err ~1e-6
__device__ __forceinline__ float tanhe(float v) {
    return 1.f - __fdividef(2.f, __expf(2.f * v) + 1.f);
}
__device__ __forceinline__ float lrelu(float v) { return v > 0.f ? v : 0.01f * v; }

__device__ __forceinline__ void fma2(u64& d, u64 a, u64 b) {
    asm("fma.rn.f32x2 %0, %1, %2, %3;" : "=l"(d) : "l"(a), "l"(b), "l"(d));
}
__device__ __forceinline__ u64 pack2(float lo, float hi) {
    u64 r;
    asm("mov.b64 %0, {%1, %2};" : "=l"(r) : "f"(lo), "f"(hi));
    return r;
}
__device__ __forceinline__ float upk(u64 a, float bias) {
    float lo = __uint_as_float((unsigned)(a & 0xffffffffu));
    float hi = __uint_as_float((unsigned)(a >> 32));
    return lo + hi + bias;
}

// ============================================================================
// ENCODER: fused 2-layer GRU, gates fully in registers.
// Warp = SPG samples; lane og owns outputs o = j*32+og, j=0..5
//   j=0,1 -> r(og), r(og+32); j=2,3 -> z; j=4,5 -> n  (one thread holds the
//   full GRU elementwise for hidden indices {og, og+32} of its samples).
// ============================================================================

// One GEMM pass: aRZ[j<4] accumulate (ACCRZ) or init; aN always fresh.
// Weights k-paired: W2[(k2*6+j)*32 + og] (u64). Input stride KDIM/2 u64.
template <int SPG, int KDIM, bool ACCRZ>
__device__ __forceinline__ void gemm_pass(const float* __restrict__ inp,
                                          const float* __restrict__ Wp,
                                          u64 (&aRZ)[SPG][4], u64 (&aN)[SPG][2],
                                          int og, int sg)
{
    const u64* W2 = reinterpret_cast<const u64*>(Wp);
    const u64* I2 = reinterpret_cast<const u64*>(inp);
#pragma unroll
    for (int p = 0; p < SPG; p++) {
        if (!ACCRZ) { aRZ[p][0] = 0; aRZ[p][1] = 0; aRZ[p][2] = 0; aRZ[p][3] = 0; }
        aN[p][0] = 0; aN[p][1] = 0;
    }
#pragma unroll 4
    for (int k2 = 0; k2 < KDIM / 2; k2++) {
        u64 w[6];
#pragma unroll
        for (int j = 0; j < 6; j++) w[j] = W2[(k2 * 6 + j) * 32 + og];
#pragma unroll
        for (int p = 0; p < SPG; p++) {
            u64 a = I2[(sg * SPG + p) * (KDIM / 2) + k2];
            fma2(aRZ[p][0], a, w[0]);
            fma2(aRZ[p][1], a, w[1]);
            fma2(aRZ[p][2], a, w[2]);
            fma2(aRZ[p][3], a, w[3]);
            fma2(aN[p][0], a, w[4]);
            fma2(aN[p][1], a, w[5]);
        }
    }
}

template <int SPG>
__global__ void __launch_bounds__(256, 1)
enc_kernel(const float* __restrict__ x,
           const float* __restrict__ Wih0, const float* __restrict__ Whh0,
           const float* __restrict__ bih0, const float* __restrict__ bhh0,
           const float* __restrict__ Wih1, const float* __restrict__ Whh1,
           const float* __restrict__ bih1, const float* __restrict__ bhh1,
           float* __restrict__ out, int T)
{
    constexpr int S = 8 * SPG;
    extern __shared__ float sm[];
    float* sWih0p = sm;                      // [3*6*64]   K=6 paired
    float* sWhh0p = sWih0p + 1152;           // [32*6*64]  paired
    float* sWih1p = sWhh0p + 12288;
    float* sWhh1p = sWih1p + 12288;
    float* sbrz0  = sWhh1p + 12288;          // [128] bih0+bhh0 (r,z)
    float* sbni0  = sbrz0 + 128;             // [64]
    float* sbnh0  = sbni0 + 64;              // [64]
    float* sbrz1  = sbnh0 + 64;              // [128]
    float* sbni1  = sbrz1 + 128;
    float* sbnh1  = sbni1 + 64;
    float* sh0    = sbnh1 + 64;              // [2][S*64] double buffered
    float* sh1    = sh0 + 2 * S * 64;        // [S*64]
    float* sxt    = sh1 + S * 64;            // [2][S*6]

    const int tid = threadIdx.x;
    const int base = blockIdx.x * S;

    // paired weight layout: sW[(k2*6+j)*64 + og*2 + c] = W[(j*32+og)][2*k2+c]
    for (int idx = tid; idx < 12288; idx += 256) {
        int og2 = idx & 63;
        int j = (idx >> 6) % 6;
        int k2 = idx / 384;
        int o = j * 32 + (og2 >> 1);
        int k = k2 * 2 + (og2 & 1);
        sWhh0p[idx] = Whh0[o * 64 + k];
        sWih1p[idx] = Wih1[o * 64 + k];
        sWhh1p[idx] = Whh1[o * 64 + k];
    }
    for (int idx = tid; idx < 1152; idx += 256) {
        int og2 = idx & 63;
        int j = (idx >> 6) % 6;
        int k2 = idx / 384;     // < 3
        int o = j * 32 + (og2 >> 1);
        int k = k2 * 2 + (og2 & 1);
        sWih0p[idx] = Wih0[o * 6 + k];
    }
    if (tid < 128) {
        sbrz0[tid] = bih0[tid] + bhh0[tid];
        sbrz1[tid] = bih1[tid] + bhh1[tid];
    } else if (tid < 192) {
        int d = tid - 128;
        sbni0[d] = bih0[128 + d]; sbnh0[d] = bhh0[128 + d];
        sbni1[d] = bih1[128 + d]; sbnh1[d] = bhh1[128 + d];
    }
    for (int idx = tid; idx < 2 * S * 64; idx += 256) sh0[idx] = 0.f;
    for (int idx = tid; idx < S * 64; idx += 256) sh1[idx] = 0.f;
    // x(0)
    for (int idx = tid; idx < S * 6; idx += 256) {
        int s = idx / 6, i = idx % 6;
        int gs = base + s;
        sxt[idx] = (gs < NT) ? x[((size_t)gs * T) * 6 + i] : 0.f;
    }
    __syncthreads();

    const int og = tid & 31, sg = tid >> 5;
    constexpr int XN = S * 6;           // 432 for SPG=9
    constexpr int XR = (XN + 255) / 256;

    u64 aRZ[SPG][4], aNI[SPG][2], aNH[SPG][2];
    float hn0[SPG], hn1[SPG];

    for (int t = 0; t < T; t++) {
        const int cur = t & 1, nxt = cur ^ 1;

        // prefetch x(t+1)
        float xr[XR];
        if (t + 1 < T) {
#pragma unroll
            for (int r = 0; r < XR; r++) {
                int idx = tid + r * 256;
                if (idx < XN) {
                    int s = idx / 6, i = idx % 6;
                    int gs = base + s;
                    xr[r] = (gs < NT) ? x[((size_t)gs * T + t + 1) * 6 + i] : 0.f;
                }
            }
        }

        // -------- layer 0: x-GEMM (K=6) + hidden GEMM + EW in regs --------
        gemm_pass<SPG, 6, false>(sxt + cur * XN, sWih0p, aRZ, aNI, og, sg);
        gemm_pass<SPG, 64, true>(sh0 + cur * S * 64, sWhh0p, aRZ, aNH, og, sg);
#pragma unroll
        for (int p = 0; p < SPG; p++) {
            int s = sg * SPG + p;
            float r0 = sige(upk(aRZ[p][0], sbrz0[og]));
            float r1 = sige(upk(aRZ[p][1], sbrz0[32 + og]));
            float z0 = sige(upk(aRZ[p][2], sbrz0[64 + og]));
            float z1 = sige(upk(aRZ[p][3], sbrz0[96 + og]));
            float n0 = tanhe(upk(aNI[p][0], sbni0[og]) + r0 * upk(aNH[p][0], sbnh0[og]));
            float n1 = tanhe(upk(aNI[p][1], sbni0[32 + og]) + r1 * upk(aNH[p][1], sbnh0[32 + og]));
            float hp0 = sh0[cur * S * 64 + s * 64 + og];
            float hp1 = sh0[cur * S * 64 + s * 64 + 32 + og];
            hn0[p] = n0 + z0 * (hp0 - n0);
            hn1[p] = n1 + z1 * (hp1 - n1);
        }
        // write new h0 into the other buffer (no hazard vs readers of cur)
#pragma unroll
        for (int p = 0; p < SPG; p++) {
            int s = sg * SPG + p;
            sh0[nxt * S * 64 + s * 64 + og] = hn0[p];
            sh0[nxt * S * 64 + s * 64 + 32 + og] = hn1[p];
        }
        if (t + 1 < T) {
#pragma unroll
            for (int r = 0; r < XR; r++) {
                int idx = tid + r * 256;
                if (idx < XN) sxt[nxt * XN + idx] = xr[r];
            }
        }
        __syncthreads();   // B1: h0[nxt] visible

        // -------- layer 1: input GEMM (h0_new) + hidden GEMM + EW --------
        gemm_pass<SPG, 64, false>(sh0 + nxt * S * 64, sWih1p, aRZ, aNI, og, sg);
        gemm_pass<SPG, 64, true>(sh1, sWhh1p, aRZ, aNH, og, sg);
#pragma unroll
        for (int p = 0; p < SPG; p++) {
            int s = sg * SPG + p;
            float r0 = sige(upk(aRZ[p][0], sbrz1[og]));
            float r1 = sige(upk(aRZ[p][1], sbrz1[32 + og]));
            float z0 = sige(upk(aRZ[p][2], sbrz1[64 + og]));
            float z1 = sige(upk(aRZ[p][3], sbrz1[96 + og]));
            float n0 = tanhe(upk(aNI[p][0], sbni1[og]) + r0 * upk(aNH[p][0], sbnh1[og]));
            float n1 = tanhe(upk(aNI[p][1], sbni1[32 + og]) + r1 * upk(aNH[p][1], sbnh1[32 + og]));
            float hp0 = sh1[s * 64 + og];
            float hp1 = sh1[s * 64 + 32 + og];
            hn0[p] = n0 + z0 * (hp0 - n0);
            hn1[p] = n1 + z1 * (hp1 - n1);
        }
        if (t == T - 1) {
#pragma unroll
            for (int p = 0; p < SPG; p++) {
                int gs = base + sg * SPG + p;
                if (gs < NT) {
                    out[(size_t)gs * 64 + og] = hn0[p];
                    out[(size_t)gs * 64 + 32 + og] = hn1[p];
                }
            }
        }
        __syncthreads();   // B2: all reads of sh1 done
#pragma unroll
        for (int p = 0; p < SPG; p++) {
            int s = sg * SPG + p;
            sh1[s * 64 + og] = hn0[p];
            sh1[s * 64 + 32 + og] = hn1[p];
        }
    }
}

// ============================================================================
// ALSTM path: previous smem-gate GRU (unchanged, known-good)
// ============================================================================
template <int SPG, int MODE>
__device__ __forceinline__ void gpass(const float* __restrict__ inp,
                                      const float* __restrict__ Wp,
                                      const float* __restrict__ bias,
                                      float* __restrict__ sgB,
                                      float* __restrict__ sgA,
                                      int og, int sg)
{
    u64 acc[SPG][6];
#pragma unroll
    for (int p = 0; p < SPG; p++)
#pragma unroll
        for (int j = 0; j < 6; j++) acc[p][j] = 0ull;

    const u64* W2 = reinterpret_cast<const u64*>(Wp);
    const u64* I2 = reinterpret_cast<const u64*>(inp);
#pragma unroll 4
    for (int k2 = 0; k2 < 32; k2++) {
        u64 w[6];
#pragma unroll
        for (int j = 0; j < 6; j++) w[j] = W2[(k2 * 6 + j) * 32 + og];
#pragma unroll
        for (int p = 0; p < SPG; p++) {
            u64 a = I2[(sg * SPG + p) * 32 + k2];
#pragma unroll
            for (int j = 0; j < 6; j++) fma2(acc[p][j], a, w[j]);
        }
    }
#pragma unroll
    for (int p = 0; p < SPG; p++) {
        int s = sg * SPG + p;
#pragma unroll
        for (int j = 0; j < 6; j++) {
            int o = j * 32 + og;
            float r = upk(acc[p][j], bias[o]);
            if (MODE == 0) sgB[s * 192 + o] = r;
            else if (j < 4) sgB[s * 192 + o] += r;
            else sgA[s * 64 + (o - 128)] = r;
        }
    }
}

template <int S, int SPG>
__global__ void __launch_bounds__(256, 1)
gru2a_kernel(const float* __restrict__ x,
             const float* __restrict__ Wih0, const float* __restrict__ Whh0,
             const float* __restrict__ bih0, const float* __restrict__ bhh0,
             const float* __restrict__ Wih1, const float* __restrict__ Whh1,
             const float* __restrict__ bih1, const float* __restrict__ bhh1,
             float* __restrict__ out, int T)
{
    extern __shared__ float sm[];
    float* sWih0 = sm;
    float* sWhh0 = sWih0 + 64 * 192;
    float* sWih1 = sWhh0 + 64 * 192;
    float* sWhh1 = sWih1 + 64 * 192;
    float* sb    = sWhh1 + 64 * 192;
    float* sh0   = sb + 768;
    float* sh1   = sh0 + S * 64;
    float* sgB   = sh1 + S * 64;
    float* sgA   = sgB + S * 192;
    float* sxt   = sgA + S * 64;

    const int tid = threadIdx.x;
    for (int idx = tid; idx < 64 * 192; idx += 256) {
        int og2 = idx & 63;
        int j = (idx >> 6) % 6;
        int k2 = idx / 384;
        int o = j * 32 + (og2 >> 1);
        int k = k2 * 2 + (og2 & 1);
        sWih0[idx] = Wih0[o * 64 + k];
        sWhh0[idx] = Whh0[o * 64 + k];
        sWih1[idx] = Wih1[o * 64 + k];
        sWhh1[idx] = Whh1[o * 64 + k];
    }
    for (int idx = tid; idx < 192; idx += 256) {
        sb[idx] = bih0[idx]; sb[192 + idx] = bhh0[idx];
        sb[384 + idx] = bih1[idx]; sb[576 + idx] = bhh1[idx];
    }
    const int base = blockIdx.x * S;
    for (int idx = tid; idx < S * 64; idx += 256) { sh0[idx] = 0.f; sh1[idx] = 0.f; }
    __syncthreads();

    const int og = tid & 31, sg = tid >> 5;

    for (int t = 0; t < T; t++) {
        for (int idx = tid; idx < S * 64; idx += 256) {
            int s = idx >> 6, i = idx & 63;
            sxt[idx] = x[((size_t)(base + s) * T + t) * 64 + i];
        }
        __syncthreads();

        gpass<SPG, 0>(sxt, sWih0, sb,       sgB, sgA, og, sg);
        gpass<SPG, 1>(sh0, sWhh0, sb + 192, sgB, sgA, og, sg);
        __syncthreads();
        for (int idx = tid; idx < S * 64; idx += 256) {
            int s = idx >> 6, j = idx & 63;
            float r = sige(sgB[s * 192 + j]);
            float z = sige(sgB[s * 192 + 64 + j]);
            float nn = tanhe(sgB[s * 192 + 128 + j] + r * sgA[s * 64 + j]);
            sh0[idx] = nn + z * (sh0[idx] - nn);
        }
        __syncthreads();

        gpass<SPG, 0>(sh0, sWih1, sb + 384, sgB, sgA, og, sg);
        gpass<SPG, 1>(sh1, sWhh1, sb + 576, sgB, sgA, og, sg);
        __syncthreads();
        for (int idx = tid; idx < S * 64; idx += 256) {
            int s = idx >> 6, j = idx & 63;
            float r = sige(sgB[s * 192 + j]);
            float z = sige(sgB[s * 192 + 64 + j]);
            float nn = tanhe(sgB[s * 192 + 128 + j] + r * sgA[s * 64 + j]);
            float h = nn + z * (sh1[idx] - nn);
            sh1[idx] = h;
            out[((size_t)(base + s) * T + t) * 64 + j] = h;
        }
        __syncthreads();
    }
}

// v_dst = trans_W^T a[:64], v_src = trans_W^T a[64:], plus bias dots.
__global__ void prep_kernel(const float* __restrict__ tW, const float* __restrict__ tb,
                            const float* __restrict__ a)
{
    int d = threadIdx.x;  // 64 threads
    float vd = 0.f, vs = 0.f;
    for (int o = 0; o < 64; o++) {
        vd = fmaf(tW[o * 64 + d], a[o], vd);
        vs = fmaf(tW[o * 64 + d], a[64 + o], vs);
    }
    g_vec[d] = vd; g_vec[64 + d] = vs;
    if (d == 0) {
        float cd = 0.f, cs = 0.f;
        for (int o = 0; o < 64; o++) { cd = fmaf(tb[o], a[o], cd); cs = fmaf(tb[o], a[64 + o], cs); }
        g_vec[128] = cd; g_vec[129] = cs;
    }
}

// Per-node src/dst scores: warp per node. grid = NT/8, 256 threads.
__global__ void score_kernel()
{
    int w = threadIdx.x >> 5, l = threadIdx.x & 31;
    int n = blockIdx.x * 8 + w;
    const float* hr = g_hlast + (size_t)n * 64;
    float h0 = hr[l], h1 = hr[l + 32];
    float ps = h0 * g_vec[64 + l] + h1 * g_vec[96 + l];
    float pd = h0 * g_vec[l] + h1 * g_vec[32 + l];
#pragma unroll
    for (int off = 16; off; off >>= 1) {
        ps += __shfl_xor_sync(~0u, ps, off);
        pd += __shfl_xor_sync(~0u, pd, off);
    }
    if (l == 0) { g_ssrc[n] = ps + g_vec[129]; g_sdst[n] = pd + g_vec[128]; }
}

// Dense GAT attention + aggregate + residual. grid = KG*7 (group x 74-row chunk).
// Warp owns up to 10 rows, processed in register batches of 8: one h-LDS.64
// per j serves all rows in the batch.
__global__ void att_kernel()
{
    extern __shared__ float sm[];
    float* sh = sm;                 // [512*64]
    float* sd = sm + 512 * 64;      // [512]
    float* se = sd + 512;           // [8 warps][8 rows][128]
    int k = blockIdx.x / 7, chunk = blockIdx.x % 7;
    int rstart = chunk * 74;
    int rend = rstart + 74; if (rend > 512) rend = 512;
    int tid = threadIdx.x, l = tid & 31, w = tid >> 5;
    const float* hg = g_hlast + (size_t)k * 512 * 64;
    for (int i = tid; i < 512 * 64; i += 256) sh[i] = hg[i];
    for (int i = tid; i < 512; i += 256) sd[i] = g_sdst[k * 512 + i];
    __syncthreads();

    // group max of s_dst (lrelu monotone -> row max = lrelu(s_src_i + dmax))
    float dm = -1e30f;
    for (int i = l; i < 512; i += 32) dm = fmaxf(dm, sd[i]);
#pragma unroll
    for (int off = 16; off; off >>= 1) dm = fmaxf(dm, __shfl_xor_sync(~0u, dm, off));

    // warp w owns rows [rstart + w*10, ...) (last warp gets the remainder)
    int myr0 = rstart + w * 10;
    int myr1 = myr0 + 10; if (myr1 > rend) myr1 = rend;
    const u64* sh2 = reinterpret_cast<const u64*>(sh);
    float* ew = se + w * 1024;

    for (int b0 = myr0; b0 < myr1; b0 += 8) {
        int cnt = myr1 - b0; if (cnt > 8) cnt = 8;
        float si[8], mi[8], den[8];
        u64 acc[8];
#pragma unroll
        for (int i = 0; i < 8; i++) {
            si[i] = (i < cnt) ? g_ssrc[k * 512 + b0 + i] : 0.f;
            mi[i] = lrelu(si[i] + dm);
            den[i] = 0.f; acc[i] = 0ull;
        }
        for (int jt = 0; jt < 4; jt++) {
#pragma unroll
            for (int i = 0; i < 8; i++) {
                if (i < cnt) {
#pragma unroll
                    for (int q = 0; q < 4; q++) {
                        int j = jt * 128 + q * 32 + l;
                        float e = __expf(lrelu(si[i] + sd[j]) - mi[i]);
                        ew[i * 128 + q * 32 + l] = e;
                        den[i] += e;
                    }
                }
            }
            __syncwarp();
#pragma unroll 4
            for (int j0 = 0; j0 < 128; j0++) {
                int j = jt * 128 + j0;
                u64 hv = sh2[j * 32 + l];
#pragma unroll
                for (int i = 0; i < 8; i++) {
                    if (i < cnt) {
                        float e = ew[i * 128 + j0];
                        fma2(acc[i], pack2(e, e), hv);
                    }
                }
            }
            __syncwarp();
        }
#pragma unroll
        for (int i = 0; i < 8; i++) {
            if (i < cnt) {
                float d = den[i];
#pragma unroll
                for (int off = 16; off; off >>= 1) d += __shfl_xor_sync(~0u, d, off);
                float inv = __fdividef(1.f, d);
                int r = b0 + i;
                float a0 = __uint_as_float((unsigned)(acc[i] & 0xffffffffu));
                float a1 = __uint_as_float((unsigned)(acc[i] >> 32));
                float* o = g_hatt + ((size_t)k * 512 + r) * 64;
                o[2 * l]     = fmaf(a0, inv, sh[r * 64 + 2 * l]);
                o[2 * l + 1] = fmaf(a1, inv, sh[r * 64 + 2 * l + 1]);
            }
        }
    }
}

// hfc = hatt @ fc_W^T + fc_b ([m][K][64] layout); z = tanh(hfc @ al_in_W^T + al_in_b).
__global__ void fc_kernel(const float* __restrict__ fcW, const float* __restrict__ fcb,
                          const float* __restrict__ inW, const float* __restrict__ inb)
{
    __shared__ float sWf[64 * 64], sWi[64 * 64], sbf[64], sbi[64];
    __shared__ float srow[8][64], shf[8][64];
    int tid = threadIdx.x;
    for (int i = tid; i < 4096; i += 256) {
        int o = i >> 6, d = i & 63;
        sWf[d * 64 + o] = fcW[i];
        sWi[d * 64 + o] = inW[i];
    }
    if (tid < 64) { sbf[tid] = fcb[tid]; sbi[tid] = inb[tid]; }
    __syncthreads();
    int w = tid >> 5, l = tid & 31;
    for (int it = 0; it < 16; it++) {
        int n = blockIdx.x * 128 + it * 8 + w;  // 80*128 = 10240
        const float* hr = g_hatt + (size_t)n * 64;
        srow[w][l] = hr[l]; srow[w][l + 32] = hr[l + 32];
        __syncwarp();
        float a0 = sbf[l], a1 = sbf[l + 32];
        for (int d = 0; d < 64; d++) {
            float v = srow[w][d];
            a0 = fmaf(v, sWf[d * 64 + l], a0);
            a1 = fmaf(v, sWf[d * 64 + l + 32], a1);
        }
        int kk = n >> 9, ii = n & 511;
        float* of = g_hfc + ((size_t)ii * KG + kk) * 64;
        of[l] = a0; of[l + 32] = a1;
        shf[w][l] = a0; shf[w][l + 32] = a1;
        __syncwarp();
        float z0 = sbi[l], z1 = sbi[l + 32];
        for (int d = 0; d < 64; d++) {
            float v = shf[w][d];
            z0 = fmaf(v, sWi[d * 64 + l], z0);
            z1 = fmaf(v, sWi[d * 64 + l + 32], z1);
        }
        float* oz = g_z + ((size_t)ii * KG + kk) * 64;
        oz[l] = tanhe(z0); oz[l + 32] = tanhe(z1);
        __syncwarp();
    }
}

// ALSTM attention head + final outputs. Warp per sample. grid = 64.
__global__ void head_kernel(const float* __restrict__ W1, const float* __restrict__ b1,
                            const float* __restrict__ W2,
                            const float* __restrict__ Wo, const float* __restrict__ bo,
                            const float* __restrict__ fcoW, const float* __restrict__ fcob,
                            float* __restrict__ out)
{
    __shared__ float sW1[64 * 32], sb1[32], sW2[32], sWo[128], sfw[64];
    __shared__ float rbuf[8][64], sbuf[8][20];
    int tid = threadIdx.x;
    for (int i = tid; i < 2048; i += 256) { int o = i >> 6, d = i & 63; sW1[d * 32 + o] = W1[i]; }
    if (tid < 32) { sb1[tid] = b1[tid]; sW2[tid] = W2[tid]; }
    if (tid < 128) sWo[tid] = Wo[tid];
    if (tid < 64) sfw[tid] = fcoW[tid];
    __syncthreads();
    int w = tid >> 5, l = tid & 31;
    int n = blockIdx.x * 8 + w;
    const float* rn = g_r + (size_t)n * KG * 64;

    for (int k = 0; k < KG; k++) {
        rbuf[w][l] = rn[k * 64 + l]; rbuf[w][l + 32] = rn[k * 64 + l + 32];
        __syncwarp();
        float acc = sb1[l];
        for (int d = 0; d < 64; d++) acc = fmaf(rbuf[w][d], sW1[d * 32 + l], acc);
        float p = tanhe(acc) * sW2[l];
#pragma unroll
        for (int off = 16; off; off >>= 1) p += __shfl_xor_sync(~0u, p, off);
        if (l == 0) sbuf[w][k] = p;
        __syncwarp();
    }
    float sv = (l < KG) ? sbuf[w][l] : -1e30f;
    float mx = sv;
#pragma unroll
    for (int off = 16; off; off >>= 1) mx = fmaxf(mx, __shfl_xor_sync(~0u, mx, off));
    float e = (l < KG) ? __expf(sv - mx) : 0.f;
    float ssum = e;
#pragma unroll
    for (int off = 16; off; off >>= 1) ssum += __shfl_xor_sync(~0u, ssum, off);
    if (l < KG) sbuf[w][l] = __fdividef(e, ssum);
    __syncwarp();

    float a0 = 0.f, a1 = 0.f;
    for (int k = 0; k < KG; k++) {
        float wk = sbuf[w][k];
        a0 = fmaf(wk, rn[k * 64 + l], a0);
        a1 = fmaf(wk, rn[k * 64 + l + 32], a1);
    }
    float rl0 = rn[19 * 64 + l], rl1 = rn[19 * 64 + l + 32];
    float part = rl0 * sWo[l] + rl1 * sWo[l + 32] + a0 * sWo[64 + l] + a1 * sWo[96 + l];
#pragma unroll
    for (int off = 16; off; off >>= 1) part += __shfl_xor_sync(~0u, part, off);
    if (l == 0) out[n] = part + bo[0];

    const float* hf = g_hfc + (size_t)n * KG * 64 + 19 * 64;
    float pp = lrelu(hf[l]) * sfw[l] + lrelu(hf[l + 32]) * sfw[l + 32];
#pragma unroll
    for (int off = 16; off; off >>= 1) pp += __shfl_xor_sync(~0u, pp, off);
    if (l == 0) out[512 + n] = pp + fcob[0];
}

extern "C" void kernel_launch(void* const* d_in, const int* in_sizes, int n_in,
                              void* d_out, int out_size)
{
    const float* x      = (const float*)d_in[0];
    const float* Wih0   = (const float*)d_in[1];
    const float* Whh0   = (const float*)d_in[2];
    const float* bih0   = (const float*)d_in[3];
    const float* bhh0   = (const float*)d_in[4];
    const float* Wih1   = (const float*)d_in[5];
    const float* Whh1   = (const float*)d_in[6];
    const float* bih1   = (const float*)d_in[7];
    const float* bhh1   = (const float*)d_in[8];
    const float* transW = (const float*)d_in[9];
    const float* transb = (const float*)d_in[10];
    const float* avec   = (const float*)d_in[11];
    const float* fcW    = (const float*)d_in[12];
    const float* fcb    = (const float*)d_in[13];
    const float* fcoW   = (const float*)d_in[14];
    const float* fcob   = (const float*)d_in[15];
    const float* inW    = (const float*)d_in[16];
    const float* inb    = (const float*)d_in[17];
    const float* aWih0  = (const float*)d_in[18];
    const float* aWhh0  = (const float*)d_in[19];
    const float* abih0  = (const float*)d_in[20];
    const float* abhh0  = (const float*)d_in[21];
    const float* aWih1  = (const float*)d_in[22];
    const float* aWhh1  = (const float*)d_in[23];
    const float* abih1  = (const float*)d_in[24];
    const float* abhh1  = (const float*)d_in[25];
    const float* att1W  = (const float*)d_in[26];
    const float* att1b  = (const float*)d_in[27];
    const float* att2W  = (const float*)d_in[28];
    const float* outW   = (const float*)d_in[29];
    const float* outb   = (const float*)d_in[30];
    float* out = (float*)d_out;

    void *p_hlast, *p_z, *p_r;
    cudaGetSymbolAddress(&p_hlast, g_hlast);
    cudaGetSymbolAddress(&p_z, g_z);
    cudaGetSymbolAddress(&p_r, g_r);

    constexpr int SPG = 9, S = 8 * SPG;               // 72 samples/block
    const size_t smemE = (size_t)(1152 + 3 * 12288 + 512 + 2 * S * 64 + S * 64 + 2 * S * 6) * 4;
    const size_t smemA = (size_t)(4 * 64 * 192 + 768 + 8 * (64 + 64 + 192 + 64 + 64)) * 4;
    const size_t smemAtt = (size_t)(512 * 64 + 512 + 8 * 1024) * 4;

    cudaFuncSetAttribute(enc_kernel<SPG>,
                         cudaFuncAttributeMaxDynamicSharedMemorySize, (int)smemE);
    cudaFuncSetAttribute(gru2a_kernel<8, 1>,
                         cudaFuncAttributeMaxDynamicSharedMemorySize, (int)smemA);
    cudaFuncSetAttribute(att_kernel,
                         cudaFuncAttributeMaxDynamicSharedMemorySize, (int)smemAtt);

    // ---- encoder: one wave of 143 blocks x 72 samples ----
    enc_kernel<SPG><<<(NT + S - 1) / S, 256, smemE>>>(
        x, Wih0, Whh0, bih0, bhh0, Wih1, Whh1, bih1, bhh1,
        (float*)p_hlast, 60);

    // ---- GAT attention ----
    prep_kernel<<<1, 64>>>(transW, transb, avec);
    score_kernel<<<1280, 256>>>();
    att_kernel<<<KG * 7, 256, smemAtt>>>();

    // ---- fc + al_in tanh ----
    fc_kernel<<<80, 256>>>(fcW, fcb, inW, inb);

    // ---- ALSTM: fused 2-layer GRU over K=20, batch 512 ----
    gru2a_kernel<8, 1><<<64, 256, smemA>>>(
        (const float*)p_z, aWih0, aWhh0, abih0, abhh0, aWih1, aWhh1, abih1, abhh1,
        (float*)p_r, 20);

    // ---- head: ALSTM attention + outputs ----
    head_kernel<<<64, 256>>>(att1W, att1b, att2W, outW, outb, fcoW, fcob, out);
}

// round 6
// speedup vs baseline: 1.5207x; 1.1056x over previous
#include <cuda_runtime.h>
#include <cstddef>

#define NT 10240
#define KG 20
#define MG 512

typedef unsigned long long u64;

// ---- scratch (device globals; allocation is forbidden) ----
__device__ float g_hlast[NT * 64];
__device__ float g_ssrc[NT];
__device__ float g_sdst[NT];
__device__ float g_hatt[NT * 64];
__device__ float g_hfc[NT * 64];   // layout [m][K][64]
__device__ float g_z[NT * 64];     // layout [m][K][64]
__device__ float g_r[NT * 64];     // layout [m][K][64]
__device__ float g_vec[130];       // v_dst[64] | v_src[64] | c_dst | c_src

__device__ __forceinline__ float sige(float v) {
    return __fdividef(1.f, 1.f + __expf(-v));
}
// tanh(x) = 1 - 2/(e^{2x}+1); NaN-safe at +/-inf, rel err ~1e-6
__device__ __forceinline__ float tanhe(float v) {
    return 1.f - __fdividef(2.f, __expf(2.f * v) + 1.f);
}
__device__ __forceinline__ float lrelu(float v) { return v > 0.f ? v : 0.01f * v; }

__device__ __forceinline__ void fma2(u64& d, u64 a, u64 b) {
    asm("fma.rn.f32x2 %0, %1, %2, %3;" : "=l"(d) : "l"(a), "l"(b), "l"(d));
}
__device__ __forceinline__ u64 pack2(float lo, float hi) {
    u64 r;
    asm("mov.b64 %0, {%1, %2};" : "=l"(r) : "f"(lo), "f"(hi));
    return r;
}
__device__ __forceinline__ float upk(u64 a, float bias) {
    float lo = __uint_as_float((unsigned)(a & 0xffffffffu));
    float hi = __uint_as_float((unsigned)(a >> 32));
    return lo + hi + bias;
}

// ============================================================================
// ENCODER: fused 2-layer GRU, gates fully in registers.
// Warp = SPG samples; lane og owns outputs o = j*32+og, j=0..5
// ============================================================================

template <int SPG, int KDIM, bool ACCRZ>
__device__ __forceinline__ void gemm_pass(const float* __restrict__ inp,
                                          const float* __restrict__ Wp,
                                          u64 (&aRZ)[SPG][4], u64 (&aN)[SPG][2],
                                          int og, int sg)
{
    const u64* W2 = reinterpret_cast<const u64*>(Wp);
    const u64* I2 = reinterpret_cast<const u64*>(inp);
#pragma unroll
    for (int p = 0; p < SPG; p++) {
        if (!ACCRZ) { aRZ[p][0] = 0; aRZ[p][1] = 0; aRZ[p][2] = 0; aRZ[p][3] = 0; }
        aN[p][0] = 0; aN[p][1] = 0;
    }
#pragma unroll 4
    for (int k2 = 0; k2 < KDIM / 2; k2++) {
        u64 w[6];
#pragma unroll
        for (int j = 0; j < 6; j++) w[j] = W2[(k2 * 6 + j) * 32 + og];
#pragma unroll
        for (int p = 0; p < SPG; p++) {
            u64 a = I2[(sg * SPG + p) * (KDIM / 2) + k2];
            fma2(aRZ[p][0], a, w[0]);
            fma2(aRZ[p][1], a, w[1]);
            fma2(aRZ[p][2], a, w[2]);
            fma2(aRZ[p][3], a, w[3]);
            fma2(aN[p][0], a, w[4]);
            fma2(aN[p][1], a, w[5]);
        }
    }
}

// Fused dual GEMM (layer 1): input GEMM (inA,WA) + hidden GEMM (inB,WB) in one
// k2 loop. r/z accumulate jointly into aRZ; n kept split (aNI from A, aNH from B).
template <int SPG>
__device__ __forceinline__ void gemm_dual(const float* __restrict__ inA,
                                          const float* __restrict__ inB,
                                          const float* __restrict__ WA,
                                          const float* __restrict__ WB,
                                          u64 (&aRZ)[SPG][4], u64 (&aNI)[SPG][2],
                                          u64 (&aNH)[SPG][2], int og, int sg)
{
    const u64* WA2 = reinterpret_cast<const u64*>(WA);
    const u64* WB2 = reinterpret_cast<const u64*>(WB);
    const u64* IA2 = reinterpret_cast<const u64*>(inA);
    const u64* IB2 = reinterpret_cast<const u64*>(inB);
#pragma unroll
    for (int p = 0; p < SPG; p++) {
        aRZ[p][0] = 0; aRZ[p][1] = 0; aRZ[p][2] = 0; aRZ[p][3] = 0;
        aNI[p][0] = 0; aNI[p][1] = 0; aNH[p][0] = 0; aNH[p][1] = 0;
    }
#pragma unroll 2
    for (int k2 = 0; k2 < 32; k2++) {
        u64 wa[6], wb[6];
#pragma unroll
        for (int j = 0; j < 6; j++) {
            wa[j] = WA2[(k2 * 6 + j) * 32 + og];
            wb[j] = WB2[(k2 * 6 + j) * 32 + og];
        }
#pragma unroll
        for (int p = 0; p < SPG; p++) {
            u64 a = IA2[(sg * SPG + p) * 32 + k2];
            u64 b = IB2[(sg * SPG + p) * 32 + k2];
            fma2(aRZ[p][0], a, wa[0]); fma2(aRZ[p][0], b, wb[0]);
            fma2(aRZ[p][1], a, wa[1]); fma2(aRZ[p][1], b, wb[1]);
            fma2(aRZ[p][2], a, wa[2]); fma2(aRZ[p][2], b, wb[2]);
            fma2(aRZ[p][3], a, wa[3]); fma2(aRZ[p][3], b, wb[3]);
            fma2(aNI[p][0], a, wa[4]); fma2(aNI[p][1], a, wa[5]);
            fma2(aNH[p][0], b, wb[4]); fma2(aNH[p][1], b, wb[5]);
        }
    }
}

template <int SPG>
__global__ void __launch_bounds__(256, 1)
enc_kernel(const float* __restrict__ x,
           const float* __restrict__ Wih0, const float* __restrict__ Whh0,
           const float* __restrict__ bih0, const float* __restrict__ bhh0,
           const float* __restrict__ Wih1, const float* __restrict__ Whh1,
           const float* __restrict__ bih1, const float* __restrict__ bhh1,
           float* __restrict__ out, int T)
{
    constexpr int S = 8 * SPG;
    extern __shared__ float sm[];
    float* sWih0p = sm;                      // [3*6*64]   K=6 paired
    float* sWhh0p = sWih0p + 1152;           // [32*6*64]  paired
    float* sWih1p = sWhh0p + 12288;
    float* sWhh1p = sWih1p + 12288;
    float* sbrz0  = sWhh1p + 12288;          // [128] bih0+bhh0 (r,z)
    float* sbni0  = sbrz0 + 128;             // [64]
    float* sbnh0  = sbni0 + 64;              // [64]
    float* sbrz1  = sbnh0 + 64;              // [128]
    float* sbni1  = sbrz1 + 128;
    float* sbnh1  = sbni1 + 64;
    float* sh0    = sbnh1 + 64;              // [2][S*64] double buffered
    float* sh1    = sh0 + 2 * S * 64;        // [S*64]
    float* sxt    = sh1 + S * 64;            // [2][S*6]

    const int tid = threadIdx.x;
    const int base = blockIdx.x * S;

    // paired weight layout: sW[(k2*6+j)*64 + og*2 + c] = W[(j*32+og)][2*k2+c]
    for (int idx = tid; idx < 12288; idx += 256) {
        int og2 = idx & 63;
        int j = (idx >> 6) % 6;
        int k2 = idx / 384;
        int o = j * 32 + (og2 >> 1);
        int k = k2 * 2 + (og2 & 1);
        sWhh0p[idx] = Whh0[o * 64 + k];
        sWih1p[idx] = Wih1[o * 64 + k];
        sWhh1p[idx] = Whh1[o * 64 + k];
    }
    for (int idx = tid; idx < 1152; idx += 256) {
        int og2 = idx & 63;
        int j = (idx >> 6) % 6;
        int k2 = idx / 384;     // < 3
        int o = j * 32 + (og2 >> 1);
        int k = k2 * 2 + (og2 & 1);
        sWih0p[idx] = Wih0[o * 6 + k];
    }
    if (tid < 128) {
        sbrz0[tid] = bih0[tid] + bhh0[tid];
        sbrz1[tid] = bih1[tid] + bhh1[tid];
    } else if (tid < 192) {
        int d = tid - 128;
        sbni0[d] = bih0[128 + d]; sbnh0[d] = bhh0[128 + d];
        sbni1[d] = bih1[128 + d]; sbnh1[d] = bhh1[128 + d];
    }
    for (int idx = tid; idx < 2 * S * 64; idx += 256) sh0[idx] = 0.f;
    for (int idx = tid; idx < S * 64; idx += 256) sh1[idx] = 0.f;
    for (int idx = tid; idx < S * 6; idx += 256) {
        int s = idx / 6, i = idx % 6;
        int gs = base + s;
        sxt[idx] = (gs < NT) ? x[((size_t)gs * T) * 6 + i] : 0.f;
    }
    __syncthreads();

    const int og = tid & 31, sg = tid >> 5;
    constexpr int XN = S * 6;
    constexpr int XR = (XN + 255) / 256;

    u64 aRZ[SPG][4], aNI[SPG][2], aNH[SPG][2];
    float hn0[SPG], hn1[SPG];

    for (int t = 0; t < T; t++) {
        const int cur = t & 1, nxt = cur ^ 1;

        float xr[XR];
        if (t + 1 < T) {
#pragma unroll
            for (int r = 0; r < XR; r++) {
                int idx = tid + r * 256;
                if (idx < XN) {
                    int s = idx / 6, i = idx % 6;
                    int gs = base + s;
                    xr[r] = (gs < NT) ? x[((size_t)gs * T + t + 1) * 6 + i] : 0.f;
                }
            }
        }

        // -------- layer 0: x-GEMM (K=6) + hidden GEMM + EW in regs --------
        gemm_pass<SPG, 6, false>(sxt + cur * XN, sWih0p, aRZ, aNI, og, sg);
        gemm_pass<SPG, 64, true>(sh0 + cur * S * 64, sWhh0p, aRZ, aNH, og, sg);
#pragma unroll
        for (int p = 0; p < SPG; p++) {
            int s = sg * SPG + p;
            float r0 = sige(upk(aRZ[p][0], sbrz0[og]));
            float r1 = sige(upk(aRZ[p][1], sbrz0[32 + og]));
            float z0 = sige(upk(aRZ[p][2], sbrz0[64 + og]));
            float z1 = sige(upk(aRZ[p][3], sbrz0[96 + og]));
            float n0 = tanhe(upk(aNI[p][0], sbni0[og]) + r0 * upk(aNH[p][0], sbnh0[og]));
            float n1 = tanhe(upk(aNI[p][1], sbni0[32 + og]) + r1 * upk(aNH[p][1], sbnh0[32 + og]));
            float hp0 = sh0[cur * S * 64 + s * 64 + og];
            float hp1 = sh0[cur * S * 64 + s * 64 + 32 + og];
            hn0[p] = n0 + z0 * (hp0 - n0);
            hn1[p] = n1 + z1 * (hp1 - n1);
        }
#pragma unroll
        for (int p = 0; p < SPG; p++) {
            int s = sg * SPG + p;
            sh0[nxt * S * 64 + s * 64 + og] = hn0[p];
            sh0[nxt * S * 64 + s * 64 + 32 + og] = hn1[p];
        }
        if (t + 1 < T) {
#pragma unroll
            for (int r = 0; r < XR; r++) {
                int idx = tid + r * 256;
                if (idx < XN) sxt[nxt * XN + idx] = xr[r];
            }
        }
        __syncthreads();   // B1: h0[nxt] visible

        // -------- layer 1: fused dual GEMM + EW --------
        gemm_dual<SPG>(sh0 + nxt * S * 64, sh1, sWih1p, sWhh1p, aRZ, aNI, aNH, og, sg);
#pragma unroll
        for (int p = 0; p < SPG; p++) {
            int s = sg * SPG + p;
            float r0 = sige(upk(aRZ[p][0], sbrz1[og]));
            float r1 = sige(upk(aRZ[p][1], sbrz1[32 + og]));
            float z0 = sige(upk(aRZ[p][2], sbrz1[64 + og]));
            float z1 = sige(upk(aRZ[p][3], sbrz1[96 + og]));
            float n0 = tanhe(upk(aNI[p][0], sbni1[og]) + r0 * upk(aNH[p][0], sbnh1[og]));
            float n1 = tanhe(upk(aNI[p][1], sbni1[32 + og]) + r1 * upk(aNH[p][1], sbnh1[32 + og]));
            float hp0 = sh1[s * 64 + og];
            float hp1 = sh1[s * 64 + 32 + og];
            hn0[p] = n0 + z0 * (hp0 - n0);
            hn1[p] = n1 + z1 * (hp1 - n1);
        }
        if (t == T - 1) {
#pragma unroll
            for (int p = 0; p < SPG; p++) {
                int gs = base + sg * SPG + p;
                if (gs < NT) {
                    out[(size_t)gs * 64 + og] = hn0[p];
                    out[(size_t)gs * 64 + 32 + og] = hn1[p];
                }
            }
        }
        __syncthreads();   // B2
#pragma unroll
        for (int p = 0; p < SPG; p++) {
            int s = sg * SPG + p;
            sh1[s * 64 + og] = hn0[p];
            sh1[s * 64 + 32 + og] = hn1[p];
        }
    }
}

// ============================================================================
// ALSTM: register-EW 2-layer GRU, j-split across warp pairs.
// 256 thr = 4 sample-groups x 2 jh-halves. S=4 samples/block, grid=128.
// Warp (sg, jh) owns hidden indices jh*32+og of sample sg.
// Weight layout (per layer, 24576 floats):
//   sW[((k2*6 + g*2 + src)*2 + jh)*64 + og*2 + c] = W_src[(g*64+jh*32+og)*64 + 2*k2+c]
//   g in {r,z,n}, src in {ih, hh}.
// ============================================================================
__global__ void __launch_bounds__(256, 1)
alstm_kernel(const float* __restrict__ zin,
             const float* __restrict__ Wih0, const float* __restrict__ Whh0,
             const float* __restrict__ bih0, const float* __restrict__ bhh0,
             const float* __restrict__ Wih1, const float* __restrict__ Whh1,
             const float* __restrict__ bih1, const float* __restrict__ bhh1,
             float* __restrict__ outr, int T)
{
    extern __shared__ float sm[];
    float* sW0   = sm;                 // [24576]
    float* sW1   = sW0 + 24576;        // [24576]
    float* sbrz0 = sW1 + 24576;        // [128]
    float* sbni0 = sbrz0 + 128;        // [64]
    float* sbnh0 = sbni0 + 64;
    float* sbrz1 = sbnh0 + 64;
    float* sbni1 = sbrz1 + 128;
    float* sbnh1 = sbni1 + 64;
    float* sh0   = sbnh1 + 64;         // [2][256]
    float* sh1   = sh0 + 512;          // [256]
    float* sxt   = sh1 + 256;          // [2][256]

    const int tid = threadIdx.x;
    const int base = blockIdx.x * 4;

    for (int idx = tid; idx < 24576; idx += 256) {
        int og2 = idx & 63;
        int col = idx >> 6;            // 0..383
        int jh = col & 1;
        int q = col >> 1;              // 0..191 = k2*6 + g*2 + src
        int src = q % 2;
        int g = (q / 2) % 3;
        int k2 = q / 6;
        int o = g * 64 + jh * 32 + (og2 >> 1);
        int k = k2 * 2 + (og2 & 1);
        sW0[idx] = src ? Whh0[o * 64 + k] : Wih0[o * 64 + k];
        sW1[idx] = src ? Whh1[o * 64 + k] : Wih1[o * 64 + k];
    }
    if (tid < 128) {
        sbrz0[tid] = bih0[tid] + bhh0[tid];
        sbrz1[tid] = bih1[tid] + bhh1[tid];
    } else if (tid < 192) {
        int d = tid - 128;
        sbni0[d] = bih0[128 + d]; sbnh0[d] = bhh0[128 + d];
        sbni1[d] = bih1[128 + d]; sbnh1[d] = bhh1[128 + d];
    }
    for (int idx = tid; idx < 512; idx += 256) sh0[idx] = 0.f;
    sh1[tid] = 0.f;
    {   // x(0): 1 float/thread
        int s = tid >> 6, d = tid & 63;
        sxt[tid] = zin[((size_t)(base + s) * T) * 64 + d];
    }
    __syncthreads();

    const int og = tid & 31;
    const int w = tid >> 5;
    const int jh = w & 1;
    const int sg = w >> 1;             // sample index in block
    const int ol = jh * 32 + og;       // owned hidden index

    const u64* W02 = reinterpret_cast<const u64*>(sW0);
    const u64* W12 = reinterpret_cast<const u64*>(sW1);

    for (int t = 0; t < T; t++) {
        const int cur = t & 1, nxt = cur ^ 1;

        float xpre = 0.f;
        if (t + 1 < T) {
            int s = tid >> 6, d = tid & 63;
            xpre = zin[((size_t)(base + s) * T + t + 1) * 64 + d];
        }

        // -------- layer 0 --------
        {
            const u64* X2 = reinterpret_cast<const u64*>(sxt + cur * 256);
            const u64* H2 = reinterpret_cast<const u64*>(sh0 + cur * 256);
            u64 aR = 0, aZ = 0, aNIv = 0, aNHv = 0;
#pragma unroll 4
            for (int k2 = 0; k2 < 32; k2++) {
                int cb = (k2 * 6) * 2 + jh;
                u64 wri = W02[(cb + 0) * 32 + og];
                u64 wrh = W02[(cb + 2) * 32 + og];
                u64 wzi = W02[(cb + 4) * 32 + og];
                u64 wzh = W02[(cb + 6) * 32 + og];
                u64 wni = W02[(cb + 8) * 32 + og];
                u64 wnh = W02[(cb + 10) * 32 + og];
                u64 ax = X2[sg * 32 + k2];
                u64 ah = H2[sg * 32 + k2];
                fma2(aR, ax, wri); fma2(aR, ah, wrh);
                fma2(aZ, ax, wzi); fma2(aZ, ah, wzh);
                fma2(aNIv, ax, wni); fma2(aNHv, ah, wnh);
            }
            float r = sige(upk(aR, sbrz0[ol]));
            float z = sige(upk(aZ, sbrz0[64 + ol]));
            float n = tanhe(upk(aNIv, sbni0[ol]) + r * upk(aNHv, sbnh0[ol]));
            float hp = sh0[cur * 256 + sg * 64 + ol];
            float h = n + z * (hp - n);
            sh0[nxt * 256 + sg * 64 + ol] = h;
        }
        if (t + 1 < T) sxt[nxt * 256 + tid] = xpre;
        __syncthreads();   // B1

        // -------- layer 1 --------
        {
            const u64* X2 = reinterpret_cast<const u64*>(sh0 + nxt * 256);
            const u64* H2 = reinterpret_cast<const u64*>(sh1);
            u64 aR = 0, aZ = 0, aNIv = 0, aNHv = 0;
#pragma unroll 4
            for (int k2 = 0; k2 < 32; k2++) {
                int cb = (k2 * 6) * 2 + jh;
                u64 wri = W12[(cb + 0) * 32 + og];
                u64 wrh = W12[(cb + 2) * 32 + og];
                u64 wzi = W12[(cb + 4) * 32 + og];
                u64 wzh = W12[(cb + 6) * 32 + og];
                u64 wni = W12[(cb + 8) * 32 + og];
                u64 wnh = W12[(cb + 10) * 32 + og];
                u64 ax = X2[sg * 32 + k2];
                u64 ah = H2[sg * 32 + k2];
                fma2(aR, ax, wri); fma2(aR, ah, wrh);
                fma2(aZ, ax, wzi); fma2(aZ, ah, wzh);
                fma2(aNIv, ax, wni); fma2(aNHv, ah, wnh);
            }
            float r = sige(upk(aR, sbrz1[ol]));
            float z = sige(upk(aZ, sbrz1[64 + ol]));
            float n = tanhe(upk(aNIv, sbni1[ol]) + r * upk(aNHv, sbnh1[ol]));
            float hp = sh1[sg * 64 + ol];
            float h = n + z * (hp - n);
            outr[((size_t)(base + sg) * T + t) * 64 + ol] = h;
            __syncthreads();   // B2
            sh1[sg * 64 + ol] = h;
        }
    }
}

// v_dst = trans_W^T a[:64], v_src = trans_W^T a[64:], plus bias dots.
__global__ void prep_kernel(const float* __restrict__ tW, const float* __restrict__ tb,
                            const float* __restrict__ a)
{
    int d = threadIdx.x;  // 64 threads
    float vd = 0.f, vs = 0.f;
    for (int o = 0; o < 64; o++) {
        vd = fmaf(tW[o * 64 + d], a[o], vd);
        vs = fmaf(tW[o * 64 + d], a[64 + o], vs);
    }
    g_vec[d] = vd; g_vec[64 + d] = vs;
    if (d == 0) {
        float cd = 0.f, cs = 0.f;
        for (int o = 0; o < 64; o++) { cd = fmaf(tb[o], a[o], cd); cs = fmaf(tb[o], a[64 + o], cs); }
        g_vec[128] = cd; g_vec[129] = cs;
    }
}

// Per-node src/dst scores: warp per node. grid = NT/8, 256 threads.
__global__ void score_kernel()
{
    int w = threadIdx.x >> 5, l = threadIdx.x & 31;
    int n = blockIdx.x * 8 + w;
    const float* hr = g_hlast + (size_t)n * 64;
    float h0 = hr[l], h1 = hr[l + 32];
    float ps = h0 * g_vec[64 + l] + h1 * g_vec[96 + l];
    float pd = h0 * g_vec[l] + h1 * g_vec[32 + l];
#pragma unroll
    for (int off = 16; off; off >>= 1) {
        ps += __shfl_xor_sync(~0u, ps, off);
        pd += __shfl_xor_sync(~0u, pd, off);
    }
    if (l == 0) { g_ssrc[n] = ps + g_vec[129]; g_sdst[n] = pd + g_vec[128]; }
}

// Dense GAT attention + aggregate + residual. grid = KG*4 (group x 128-row chunk).
// Warp owns exactly 16 rows = 2 batches of 8. exp weights stored pre-duplicated
// as u64 pairs; inner loop = 1 h-LDS.64 + 8 broadcast e-LDS.64 + 8 FMA2.
__global__ void att_kernel()
{
    extern __shared__ float sm[];
    float* sh = sm;                 // [512*64]
    float* sd = sm + 512 * 64;      // [512]
    u64* seb = reinterpret_cast<u64*>(sd + 512);   // [8 warps][8 rows][128]
    int k = blockIdx.x >> 2, chunk = blockIdx.x & 3;
    int tid = threadIdx.x, l = tid & 31, w = tid >> 5;
    const float* hg = g_hlast + (size_t)k * 512 * 64;
    for (int i = tid; i < 512 * 64; i += 256) sh[i] = hg[i];
    for (int i = tid; i < 512; i += 256) sd[i] = g_sdst[k * 512 + i];
    __syncthreads();

    // group max of s_dst (lrelu monotone -> row max = lrelu(s_src_i + dmax))
    float dm = -1e30f;
    for (int i = l; i < 512; i += 32) dm = fmaxf(dm, sd[i]);
#pragma unroll
    for (int off = 16; off; off >>= 1) dm = fmaxf(dm, __shfl_xor_sync(~0u, dm, off));

    const u64* sh2 = reinterpret_cast<const u64*>(sh);
    u64* ews = seb + w * 1024;

    for (int batch = 0; batch < 2; batch++) {
        int b0 = chunk * 128 + w * 16 + batch * 8;
        float si[8], mi[8], den[8];
        u64 acc[8];
#pragma unroll
        for (int i = 0; i < 8; i++) {
            si[i] = g_ssrc[k * 512 + b0 + i];
            mi[i] = lrelu(si[i] + dm);
            den[i] = 0.f; acc[i] = 0ull;
        }
        for (int jt = 0; jt < 4; jt++) {
#pragma unroll
            for (int i = 0; i < 8; i++) {
#pragma unroll
                for (int q = 0; q < 4; q++) {
                    int jj = q * 32 + l;
                    float e = __expf(lrelu(si[i] + sd[jt * 128 + jj]) - mi[i]);
                    ews[i * 128 + jj] = pack2(e, e);
                    den[i] += e;
                }
            }
            __syncwarp();
#pragma unroll 4
            for (int j0 = 0; j0 < 128; j0++) {
                u64 hv = sh2[(jt * 128 + j0) * 32 + l];
#pragma unroll
                for (int i = 0; i < 8; i++)
                    fma2(acc[i], ews[i * 128 + j0], hv);
            }
            __syncwarp();
        }
#pragma unroll
        for (int i = 0; i < 8; i++) {
            float d = den[i];
#pragma unroll
            for (int off = 16; off; off >>= 1) d += __shfl_xor_sync(~0u, d, off);
            float inv = __fdividef(1.f, d);
            int r = b0 + i;
            float a0 = __uint_as_float((unsigned)(acc[i] & 0xffffffffu));
            float a1 = __uint_as_float((unsigned)(acc[i] >> 32));
            float* o = g_hatt + ((size_t)k * 512 + r) * 64;
            o[2 * l]     = fmaf(a0, inv, sh[r * 64 + 2 * l]);
            o[2 * l + 1] = fmaf(a1, inv, sh[r * 64 + 2 * l + 1]);
        }
    }
}

// hfc = hatt @ fc_W^T + fc_b ([m][K][64] layout); z = tanh(hfc @ al_in_W^T + al_in_b).
__global__ void fc_kernel(const float* __restrict__ fcW, const float* __restrict__ fcb,
                          const float* __restrict__ inW, const float* __restrict__ inb)
{
    __shared__ float sWf[64 * 64], sWi[64 * 64], sbf[64], sbi[64];
    __shared__ float srow[8][64], shf[8][64];
    int tid = threadIdx.x;
    for (int i = tid; i < 4096; i += 256) {
        int o = i >> 6, d = i & 63;
        sWf[d * 64 + o] = fcW[i];
        sWi[d * 64 + o] = inW[i];
    }
    if (tid < 64) { sbf[tid] = fcb[tid]; sbi[tid] = inb[tid]; }
    __syncthreads();
    int w = tid >> 5, l = tid & 31;
    for (int it = 0; it < 16; it++) {
        int n = blockIdx.x * 128 + it * 8 + w;  // 80*128 = 10240
        const float* hr = g_hatt + (size_t)n * 64;
        srow[w][l] = hr[l]; srow[w][l + 32] = hr[l + 32];
        __syncwarp();
        float a0 = sbf[l], a1 = sbf[l + 32];
        for (int d = 0; d < 64; d++) {
            float v = srow[w][d];
            a0 = fmaf(v, sWf[d * 64 + l], a0);
            a1 = fmaf(v, sWf[d * 64 + l + 32], a1);
        }
        int kk = n >> 9, ii = n & 511;
        float* of = g_hfc + ((size_t)ii * KG + kk) * 64;
        of[l] = a0; of[l + 32] = a1;
        shf[w][l] = a0; shf[w][l + 32] = a1;
        __syncwarp();
        float z0 = sbi[l], z1 = sbi[l + 32];
        for (int d = 0; d < 64; d++) {
            float v = shf[w][d];
            z0 = fmaf(v, sWi[d * 64 + l], z0);
            z1 = fmaf(v, sWi[d * 64 + l + 32], z1);
        }
        float* oz = g_z + ((size_t)ii * KG + kk) * 64;
        oz[l] = tanhe(z0); oz[l + 32] = tanhe(z1);
        __syncwarp();
    }
}

// ALSTM attention head + final outputs. Warp per sample. grid = 64.
__global__ void head_kernel(const float* __restrict__ W1, const float* __restrict__ b1,
                            const float* __restrict__ W2,
                            const float* __restrict__ Wo, const float* __restrict__ bo,
                            const float* __restrict__ fcoW, const float* __restrict__ fcob,
                            float* __restrict__ out)
{
    __shared__ float sW1[64 * 32], sb1[32], sW2[32], sWo[128], sfw[64];
    __shared__ float rbuf[8][64], sbuf[8][20];
    int tid = threadIdx.x;
    for (int i = tid; i < 2048; i += 256) { int o = i >> 6, d = i & 63; sW1[d * 32 + o] = W1[i]; }
    if (tid < 32) { sb1[tid] = b1[tid]; sW2[tid] = W2[tid]; }
    if (tid < 128) sWo[tid] = Wo[tid];
    if (tid < 64) sfw[tid] = fcoW[tid];
    __syncthreads();
    int w = tid >> 5, l = tid & 31;
    int n = blockIdx.x * 8 + w;
    const float* rn = g_r + (size_t)n * KG * 64;

    for (int k = 0; k < KG; k++) {
        rbuf[w][l] = rn[k * 64 + l]; rbuf[w][l + 32] = rn[k * 64 + l + 32];
        __syncwarp();
        float acc = sb1[l];
        for (int d = 0; d < 64; d++) acc = fmaf(rbuf[w][d], sW1[d * 32 + l], acc);
        float p = tanhe(acc) * sW2[l];
#pragma unroll
        for (int off = 16; off; off >>= 1) p += __shfl_xor_sync(~0u, p, off);
        if (l == 0) sbuf[w][k] = p;
        __syncwarp();
    }
    float sv = (l < KG) ? sbuf[w][l] : -1e30f;
    float mx = sv;
#pragma unroll
    for (int off = 16; off; off >>= 1) mx = fmaxf(mx, __shfl_xor_sync(~0u, mx, off));
    float e = (l < KG) ? __expf(sv - mx) : 0.f;
    float ssum = e;
#pragma unroll
    for (int off = 16; off; off >>= 1) ssum += __shfl_xor_sync(~0u, ssum, off);
    if (l < KG) sbuf[w][l] = __fdividef(e, ssum);
    __syncwarp();

    float a0 = 0.f, a1 = 0.f;
    for (int k = 0; k < KG; k++) {
        float wk = sbuf[w][k];
        a0 = fmaf(wk, rn[k * 64 + l], a0);
        a1 = fmaf(wk, rn[k * 64 + l + 32], a1);
    }
    float rl0 = rn[19 * 64 + l], rl1 = rn[19 * 64 + l + 32];
    float part = rl0 * sWo[l] + rl1 * sWo[l + 32] + a0 * sWo[64 + l] + a1 * sWo[96 + l];
#pragma unroll
    for (int off = 16; off; off >>= 1) part += __shfl_xor_sync(~0u, part, off);
    if (l == 0) out[n] = part + bo[0];

    const float* hf = g_hfc + (size_t)n * KG * 64 + 19 * 64;
    float pp = lrelu(hf[l]) * sfw[l] + lrelu(hf[l + 32]) * sfw[l + 32];
#pragma unroll
    for (int off = 16; off; off >>= 1) pp += __shfl_xor_sync(~0u, pp, off);
    if (l == 0) out[512 + n] = pp + fcob[0];
}

extern "C" void kernel_launch(void* const* d_in, const int* in_sizes, int n_in,
                              void* d_out, int out_size)
{
    const float* x      = (const float*)d_in[0];
    const float* Wih0   = (const float*)d_in[1];
    const float* Whh0   = (const float*)d_in[2];
    const float* bih0   = (const float*)d_in[3];
    const float* bhh0   = (const float*)d_in[4];
    const float* Wih1   = (const float*)d_in[5];
    const float* Whh1   = (const float*)d_in[6];
    const float* bih1   = (const float*)d_in[7];
    const float* bhh1   = (const float*)d_in[8];
    const float* transW = (const float*)d_in[9];
    const float* transb = (const float*)d_in[10];
    const float* avec   = (const float*)d_in[11];
    const float* fcW    = (const float*)d_in[12];
    const float* fcb    = (const float*)d_in[13];
    const float* fcoW   = (const float*)d_in[14];
    const float* fcob   = (const float*)d_in[15];
    const float* inW    = (const float*)d_in[16];
    const float* inb    = (const float*)d_in[17];
    const float* aWih0  = (const float*)d_in[18];
    const float* aWhh0  = (const float*)d_in[19];
    const float* abih0  = (const float*)d_in[20];
    const float* abhh0  = (const float*)d_in[21];
    const float* aWih1  = (const float*)d_in[22];
    const float* aWhh1  = (const float*)d_in[23];
    const float* abih1  = (const float*)d_in[24];
    const float* abhh1  = (const float*)d_in[25];
    const float* att1W  = (const float*)d_in[26];
    const float* att1b  = (const float*)d_in[27];
    const float* att2W  = (const float*)d_in[28];
    const float* outW   = (const float*)d_in[29];
    const float* outb   = (const float*)d_in[30];
    float* out = (float*)d_out;

    void *p_hlast, *p_z, *p_r;
    cudaGetSymbolAddress(&p_hlast, g_hlast);
    cudaGetSymbolAddress(&p_z, g_z);
    cudaGetSymbolAddress(&p_r, g_r);

    constexpr int SPG = 9, S = 8 * SPG;               // 72 samples/block
    const size_t smemE = (size_t)(1152 + 3 * 12288 + 512 + 2 * S * 64 + S * 64 + 2 * S * 6) * 4;
    const size_t smemA = (size_t)(2 * 24576 + 512 + 2 * 256 + 256 + 2 * 256) * 4;
    const size_t smemAtt = (size_t)(512 * 64 + 512) * 4 + 8 * 1024 * 8;

    cudaFuncSetAttribute(enc_kernel<SPG>,
                         cudaFuncAttributeMaxDynamicSharedMemorySize, (int)smemE);
    cudaFuncSetAttribute(alstm_kernel,
                         cudaFuncAttributeMaxDynamicSharedMemorySize, (int)smemA);
    cudaFuncSetAttribute(att_kernel,
                         cudaFuncAttributeMaxDynamicSharedMemorySize, (int)smemAtt);

    // ---- encoder: one wave of 143 blocks x 72 samples ----
    enc_kernel<SPG><<<(NT + S - 1) / S, 256, smemE>>>(
        x, Wih0, Whh0, bih0, bhh0, Wih1, Whh1, bih1, bhh1,
        (float*)p_hlast, 60);

    // ---- GAT attention ----
    prep_kernel<<<1, 64>>>(transW, transb, avec);
    score_kernel<<<1280, 256>>>();
    att_kernel<<<KG * 4, 256, smemAtt>>>();

    // ---- fc + al_in tanh ----
    fc_kernel<<<80, 256>>>(fcW, fcb, inW, inb);

    // ---- ALSTM: register-EW fused 2-layer GRU over K=20, batch 512 ----
    alstm_kernel<<<128, 256, smemA>>>(
        (const float*)p_z, aWih0, aWhh0, abih0, abhh0, aWih1, aWhh1, abih1, abhh1,
        (float*)p_r, 20);

    // ---- head: ALSTM attention + outputs ----
    head_kernel<<<64, 256>>>(att1W, att1b, att2W, outW, outb, fcoW, fcob, out);
}